// round 1
// baseline (speedup 1.0000x reference)
#include <cuda_runtime.h>

// Problem constants
#define Bsz 8
#define CI  512
#define CO  256
#define NN  2048   // T*H*W = 8*16*16

// Scratch (device globals; no allocation allowed in kernel_launch)
__device__ float g_K[Bsz * CO * NN];          // [B][Co][N]
__device__ float g_Q[Bsz * CO * NN];          // [B][Co][N]
__device__ float g_V[Bsz * CO * NN];          // [B][Co][N]
__device__ float g_S[Bsz * NN * NN];          // [B][N][N] attention logits/probs (134MB)
__device__ float g_O[Bsz * NN * CO];          // [B][N][Co] (raw-reshape view => [B][Co][N])

// ---------------- GEMM tiling ----------------
#define BM  128
#define BN  128
#define BK  16
#define PAD 4
#define NTHREADS 256

// Load a BKxBM tile from a k-major source: src[k][m], m contiguous, row stride ld.
// sm[k][m] = src[k*ld + m]. src pre-offset to (k0, m0).
__device__ __forceinline__ void load_tile_kmajor(float (*sm)[BM + PAD],
                                                 const float* __restrict__ src,
                                                 int ld, int tid) {
#pragma unroll
    for (int i = 0; i < 2; i++) {
        int f  = tid + i * NTHREADS;      // float4 index, 512 total
        int k  = f >> 5;                  // 32 float4 per row (128 floats)
        int m4 = (f & 31) << 2;
        float4 v = *reinterpret_cast<const float4*>(src + (size_t)k * ld + m4);
        *reinterpret_cast<float4*>(&sm[k][m4]) = v;
    }
}

// Load a BMxBK tile from an m-major source: src[m][k], k contiguous, row stride ld.
// Transposed on store: sm[k][m] = src[m*ld + k]. src pre-offset to (m0, k0).
__device__ __forceinline__ void load_tile_mmajor(float (*sm)[BM + PAD],
                                                 const float* __restrict__ src,
                                                 int ld, int tid) {
#pragma unroll
    for (int i = 0; i < 2; i++) {
        int f  = tid + i * NTHREADS;      // float4 index
        int m  = f >> 2;                  // 4 float4 per row (16 floats)
        int kq = (f & 3) << 2;
        float4 v = *reinterpret_cast<const float4*>(src + (size_t)m * ld + kq);
        sm[kq + 0][m] = v.x;
        sm[kq + 1][m] = v.y;
        sm[kq + 2][m] = v.z;
        sm[kq + 3][m] = v.w;
    }
}

__device__ __forceinline__ void mm_compute(float (*As)[BM + PAD], float (*Bs)[BN + PAD],
                                           float acc[8][8], int trow, int tcol) {
#pragma unroll
    for (int k = 0; k < BK; k++) {
        float a[8], b[8];
        *reinterpret_cast<float4*>(a)     = *reinterpret_cast<float4*>(&As[k][trow * 8]);
        *reinterpret_cast<float4*>(a + 4) = *reinterpret_cast<float4*>(&As[k][trow * 8 + 4]);
        *reinterpret_cast<float4*>(b)     = *reinterpret_cast<float4*>(&Bs[k][tcol * 8]);
        *reinterpret_cast<float4*>(b + 4) = *reinterpret_cast<float4*>(&Bs[k][tcol * 8 + 4]);
#pragma unroll
        for (int i = 0; i < 8; i++)
#pragma unroll
            for (int j = 0; j < 8; j++)
                acc[i][j] += a[i] * b[j];
    }
}

// ---------------- Stage 1: K/Q/V projections ----------------
// C[co][n] = sum_ci W[co][ci] * X[b][ci][n] + bias[co]
// grid: (NN/BN, CO/BM, Bsz*3)
__global__ __launch_bounds__(NTHREADS)
void kqv_kernel(const float* __restrict__ x, const float* __restrict__ query,
                const float* __restrict__ kw, const float* __restrict__ kb,
                const float* __restrict__ vw, const float* __restrict__ vb,
                const float* __restrict__ qw, const float* __restrict__ qb) {
    int z = blockIdx.z;
    int b = z / 3, which = z % 3;
    const float *W, *bias, *X;
    float* out;
    if (which == 0)      { W = kw; bias = kb; X = x;     out = g_K; }
    else if (which == 1) { W = qw; bias = qb; X = query; out = g_Q; }
    else                 { W = vw; bias = vb; X = x;     out = g_V; }
    X   += (size_t)b * CI * NN;
    out += (size_t)b * CO * NN;

    int n0  = blockIdx.x * BN;
    int co0 = blockIdx.y * BM;
    int tid = threadIdx.x, trow = tid >> 4, tcol = tid & 15;

    __shared__ float As[BK][BM + PAD];
    __shared__ float Bs[BK][BN + PAD];
    float acc[8][8] = {};

    for (int k0 = 0; k0 < CI; k0 += BK) {
        load_tile_mmajor(As, W + (size_t)co0 * CI + k0, CI, tid);  // W[co][ci]
        load_tile_kmajor(Bs, X + (size_t)k0 * NN + n0, NN, tid);   // X[ci][n]
        __syncthreads();
        mm_compute(As, Bs, acc, trow, tcol);
        __syncthreads();
    }

#pragma unroll
    for (int i = 0; i < 8; i++) {
        int r = co0 + trow * 8 + i;
        float bv = bias[r];
        float4 v0 = make_float4(acc[i][0] + bv, acc[i][1] + bv, acc[i][2] + bv, acc[i][3] + bv);
        float4 v1 = make_float4(acc[i][4] + bv, acc[i][5] + bv, acc[i][6] + bv, acc[i][7] + bv);
        float* dst = out + (size_t)r * NN + n0 + tcol * 8;
        *reinterpret_cast<float4*>(dst)     = v0;
        *reinterpret_cast<float4*>(dst + 4) = v1;
    }
}

// ---------------- Stage 2: S = K^T Q / 16 ----------------
// S[n][m] = (1/16) sum_c K[c][n] Q[c][m]
// grid: (NN/BN, NN/BM, Bsz)
__global__ __launch_bounds__(NTHREADS)
void qk_kernel() {
    int b = blockIdx.z;
    const float* K = g_K + (size_t)b * CO * NN;
    const float* Q = g_Q + (size_t)b * CO * NN;
    float* S = g_S + (size_t)b * NN * NN;

    int m0 = blockIdx.x * BN;   // query index (cols)
    int n0 = blockIdx.y * BM;   // key index (rows)
    int tid = threadIdx.x, trow = tid >> 4, tcol = tid & 15;

    __shared__ float As[BK][BM + PAD];
    __shared__ float Bs[BK][BN + PAD];
    float acc[8][8] = {};

    for (int k0 = 0; k0 < CO; k0 += BK) {
        load_tile_kmajor(As, K + (size_t)k0 * NN + n0, NN, tid);
        load_tile_kmajor(Bs, Q + (size_t)k0 * NN + m0, NN, tid);
        __syncthreads();
        mm_compute(As, Bs, acc, trow, tcol);
        __syncthreads();
    }

    const float scale = 0.0625f;  // 1/sqrt(256)
#pragma unroll
    for (int i = 0; i < 8; i++) {
        int r = n0 + trow * 8 + i;
        float4 v0 = make_float4(acc[i][0] * scale, acc[i][1] * scale,
                                acc[i][2] * scale, acc[i][3] * scale);
        float4 v1 = make_float4(acc[i][4] * scale, acc[i][5] * scale,
                                acc[i][6] * scale, acc[i][7] * scale);
        float* dst = S + (size_t)r * NN + m0 + tcol * 8;
        *reinterpret_cast<float4*>(dst)     = v0;
        *reinterpret_cast<float4*>(dst + 4) = v1;
    }
}

// ---------------- Stage 3: row softmax ----------------
// grid: Bsz*NN blocks of 256 threads; each row has 2048 floats (8/thread)
__global__ __launch_bounds__(256)
void softmax_kernel() {
    float* p = g_S + (size_t)blockIdx.x * NN;
    int tid = threadIdx.x;
    __shared__ float sh[9];

    float4 v0 = *reinterpret_cast<float4*>(p + tid * 8);
    float4 v1 = *reinterpret_cast<float4*>(p + tid * 8 + 4);
    float v[8] = {v0.x, v0.y, v0.z, v0.w, v1.x, v1.y, v1.z, v1.w};

    // max reduce
    float m = v[0];
#pragma unroll
    for (int i = 1; i < 8; i++) m = fmaxf(m, v[i]);
#pragma unroll
    for (int o = 16; o > 0; o >>= 1) m = fmaxf(m, __shfl_xor_sync(0xffffffffu, m, o));
    if ((tid & 31) == 0) sh[tid >> 5] = m;
    __syncthreads();
    if (tid == 0) {
        float r = sh[0];
#pragma unroll
        for (int i = 1; i < 8; i++) r = fmaxf(r, sh[i]);
        sh[8] = r;
    }
    __syncthreads();
    m = sh[8];

    // exp + sum reduce
    float s = 0.f;
#pragma unroll
    for (int i = 0; i < 8; i++) { v[i] = expf(v[i] - m); s += v[i]; }
#pragma unroll
    for (int o = 16; o > 0; o >>= 1) s += __shfl_xor_sync(0xffffffffu, s, o);
    __syncthreads();  // protect sh reuse
    if ((tid & 31) == 0) sh[tid >> 5] = s;
    __syncthreads();
    if (tid == 0) {
        float r = sh[0];
#pragma unroll
        for (int i = 1; i < 8; i++) r += sh[i];
        sh[8] = r;
    }
    __syncthreads();
    float inv = 1.0f / sh[8];

    float4 o0 = make_float4(v[0] * inv, v[1] * inv, v[2] * inv, v[3] * inv);
    float4 o1 = make_float4(v[4] * inv, v[5] * inv, v[6] * inv, v[7] * inv);
    *reinterpret_cast<float4*>(p + tid * 8)     = o0;
    *reinterpret_cast<float4*>(p + tid * 8 + 4) = o1;
}

// ---------------- Stage 4: O = P @ V^T ----------------
// O[n][c] = sum_m P[n][m] V[c][m];  stored [B][N][Co] row-major
// grid: (CO/BN=2, NN/BM=16, Bsz)
__global__ __launch_bounds__(NTHREADS)
void av_kernel() {
    int b = blockIdx.z;
    const float* P = g_S + (size_t)b * NN * NN;
    const float* V = g_V + (size_t)b * CO * NN;
    float* O = g_O + (size_t)b * NN * CO;

    int c0 = blockIdx.x * BN;
    int n0 = blockIdx.y * BM;
    int tid = threadIdx.x, trow = tid >> 4, tcol = tid & 15;

    __shared__ float As[BK][BM + PAD];
    __shared__ float Bs[BK][BN + PAD];
    float acc[8][8] = {};

    for (int m0 = 0; m0 < NN; m0 += BK) {
        load_tile_mmajor(As, P + (size_t)n0 * NN + m0, NN, tid);  // P[n][m]
        load_tile_mmajor(Bs, V + (size_t)c0 * NN + m0, NN, tid);  // V[c][m]
        __syncthreads();
        mm_compute(As, Bs, acc, trow, tcol);
        __syncthreads();
    }

#pragma unroll
    for (int i = 0; i < 8; i++) {
        int r = n0 + trow * 8 + i;
        float* dst = O + (size_t)r * CO + c0 + tcol * 8;
        *reinterpret_cast<float4*>(dst)     = *reinterpret_cast<float4*>(&acc[i][0]);
        *reinterpret_cast<float4*>(dst + 4) = *reinterpret_cast<float4*>(&acc[i][4]);
    }
}

// ---------------- Stage 5: up-projection + residual ----------------
// Raw-reshape: g_O per batch ([N][Co] row-major) reinterpreted as Or[Co][N].
// R[ci][n] = x[ci][n] + scaling * (sum_co up_w[ci][co] * Or[co][n] + up_b[ci])
// grid: (NN/BN, CI/BM=4, Bsz)
__global__ __launch_bounds__(NTHREADS)
void up_kernel(const float* __restrict__ x, const float* __restrict__ up_w,
               const float* __restrict__ up_b, const float* __restrict__ scaling,
               float* __restrict__ out) {
    int b = blockIdx.z;
    const float* Or = g_O + (size_t)b * CO * NN;  // view as [Co][N]
    const float* X  = x   + (size_t)b * CI * NN;
    float* R        = out + (size_t)b * CI * NN;

    int n0  = blockIdx.x * BN;
    int ci0 = blockIdx.y * BM;
    int tid = threadIdx.x, trow = tid >> 4, tcol = tid & 15;

    __shared__ float As[BK][BM + PAD];
    __shared__ float Bs[BK][BN + PAD];
    float acc[8][8] = {};

    for (int k0 = 0; k0 < CO; k0 += BK) {
        load_tile_mmajor(As, up_w + (size_t)ci0 * CO + k0, CO, tid);  // up_w[ci][co]
        load_tile_kmajor(Bs, Or + (size_t)k0 * NN + n0, NN, tid);     // Or[co][n]
        __syncthreads();
        mm_compute(As, Bs, acc, trow, tcol);
        __syncthreads();
    }

    float s = *scaling;
#pragma unroll
    for (int i = 0; i < 8; i++) {
        int r = ci0 + trow * 8 + i;
        float bb = up_b[r];
        const float* xs = X + (size_t)r * NN + n0 + tcol * 8;
        float* dst      = R + (size_t)r * NN + n0 + tcol * 8;
        float4 x0 = *reinterpret_cast<const float4*>(xs);
        float4 x1 = *reinterpret_cast<const float4*>(xs + 4);
        float4 o0 = make_float4(x0.x + s * (acc[i][0] + bb), x0.y + s * (acc[i][1] + bb),
                                x0.z + s * (acc[i][2] + bb), x0.w + s * (acc[i][3] + bb));
        float4 o1 = make_float4(x1.x + s * (acc[i][4] + bb), x1.y + s * (acc[i][5] + bb),
                                x1.z + s * (acc[i][6] + bb), x1.w + s * (acc[i][7] + bb));
        *reinterpret_cast<float4*>(dst)     = o0;
        *reinterpret_cast<float4*>(dst + 4) = o1;
    }
}

// ---------------- launch ----------------
extern "C" void kernel_launch(void* const* d_in, const int* in_sizes, int n_in,
                              void* d_out, int out_size) {
    const float* x       = (const float*)d_in[0];
    const float* query   = (const float*)d_in[1];
    const float* key_w   = (const float*)d_in[2];
    const float* key_b   = (const float*)d_in[3];
    const float* val_w   = (const float*)d_in[4];
    const float* val_b   = (const float*)d_in[5];
    const float* query_w = (const float*)d_in[6];
    const float* query_b = (const float*)d_in[7];
    const float* up_w    = (const float*)d_in[8];
    const float* up_b    = (const float*)d_in[9];
    const float* scaling = (const float*)d_in[10];
    float* out = (float*)d_out;

    dim3 thr(NTHREADS);
    kqv_kernel<<<dim3(NN / BN, CO / BM, Bsz * 3), thr>>>(x, query, key_w, key_b,
                                                         val_w, val_b, query_w, query_b);
    qk_kernel<<<dim3(NN / BN, NN / BM, Bsz), thr>>>();
    softmax_kernel<<<dim3(Bsz * NN), 256>>>();
    av_kernel<<<dim3(CO / BN, NN / BM, Bsz), thr>>>();
    up_kernel<<<dim3(NN / BN, CI / BM, Bsz), thr>>>(x, up_w, up_b, scaling, out);
}

// round 3
// speedup vs baseline: 1.9778x; 1.9778x over previous
#include <cuda_runtime.h>
#include <cuda_bf16.h>
#include <cstdint>

#define Bsz 8
#define CI  512
#define CO  256
#define NN  2048

// ---------------- scratch (device globals, bf16) ----------------
__device__ unsigned short g_Kt[(size_t)Bsz * NN * CO];  // [b][n][co]
__device__ unsigned short g_Qt[(size_t)Bsz * NN * CO];  // [b][n][co]
__device__ unsigned short g_V [(size_t)Bsz * CO * NN];  // [b][co][n]
__device__ unsigned short g_S [(size_t)Bsz * NN * NN];  // [b][n][m] logits -> probs
__device__ unsigned short g_O [(size_t)Bsz * NN * CO];  // [b][n][co]; raw view == [co2][n2]

// ---------------- helpers ----------------
__device__ __forceinline__ uint32_t smem_u32(const void* p) {
    uint32_t a;
    asm("{ .reg .u64 t; cvta.to.shared.u64 t, %1; cvt.u32.u64 %0, t; }" : "=r"(a) : "l"(p));
    return a;
}
__device__ __forceinline__ void sts64(uint32_t addr, uint32_t a, uint32_t b) {
    asm volatile("st.shared.v2.b32 [%0], {%1, %2};" :: "r"(addr), "r"(a), "r"(b));
}
__device__ __forceinline__ void sts16(uint32_t addr, unsigned short v) {
    asm volatile("st.shared.b16 [%0], %1;" :: "r"(addr), "h"(v));
}
__device__ __forceinline__ void ldmatrix_x4(uint32_t* r, uint32_t addr) {
    asm volatile("ldmatrix.sync.aligned.m8n8.x4.shared.b16 {%0,%1,%2,%3}, [%4];"
                 : "=r"(r[0]), "=r"(r[1]), "=r"(r[2]), "=r"(r[3]) : "r"(addr));
}
__device__ __forceinline__ void mma16816(float* d, const uint32_t* a, const uint32_t* b) {
    asm volatile(
        "mma.sync.aligned.m16n8k16.row.col.f32.bf16.bf16.f32 "
        "{%0,%1,%2,%3}, {%4,%5,%6,%7}, {%8,%9}, {%0,%1,%2,%3};"
        : "+f"(d[0]), "+f"(d[1]), "+f"(d[2]), "+f"(d[3])
        : "r"(a[0]), "r"(a[1]), "r"(a[2]), "r"(a[3]), "r"(b[0]), "r"(b[1]));
}

// smem tile geometry: 128 rows x 32 halves (BK), padded to 40 halves (80 B/row)
#define BK   32
#define ROWH 40
#define ROWB 80

// ---------------- tile loaders: write [row][k] bf16 into padded smem ----------------
// src row-major [row][k], k contiguous, row stride ld (bf16)
__device__ __forceinline__ void ld_rm_bf16(uint32_t sb, const unsigned short* __restrict__ src,
                                           int ld, int tid) {
#pragma unroll
    for (int i = 0; i < 4; i++) {
        int f = tid + i * 256;              // 1024 uint2 = 128 rows x 8
        int row = f >> 3, kc = (f & 7) << 2;
        uint2 v = *reinterpret_cast<const uint2*>(src + (size_t)row * ld + kc);
        sts64(sb + row * ROWB + kc * 2, v.x, v.y);
    }
}
// src row-major [row][k] fp32
__device__ __forceinline__ void ld_rm_f32(uint32_t sb, const float* __restrict__ src,
                                          int ld, int tid) {
#pragma unroll
    for (int i = 0; i < 4; i++) {
        int f = tid + i * 256;
        int row = f >> 3, kc = (f & 7) << 2;
        float4 v = *reinterpret_cast<const float4*>(src + (size_t)row * ld + kc);
        __nv_bfloat162 lo = __floats2bfloat162_rn(v.x, v.y);
        __nv_bfloat162 hi = __floats2bfloat162_rn(v.z, v.w);
        sts64(sb + row * ROWB + kc * 2,
              *reinterpret_cast<uint32_t*>(&lo), *reinterpret_cast<uint32_t*>(&hi));
    }
}
// src [k][m] fp32 (m contiguous): tile[m][k] = src[k*ld + m]
__device__ __forceinline__ void ld_tr_f32(uint32_t sb, const float* __restrict__ src,
                                          int ld, int tid) {
#pragma unroll
    for (int i = 0; i < 4; i++) {
        int f = tid + i * 256;              // 1024 float4 = 32 k x 32 m4
        int k = f >> 5, m4 = (f & 31) << 2;
        float4 v = *reinterpret_cast<const float4*>(src + (size_t)k * ld + m4);
        __nv_bfloat16 h0 = __float2bfloat16(v.x), h1 = __float2bfloat16(v.y);
        __nv_bfloat16 h2 = __float2bfloat16(v.z), h3 = __float2bfloat16(v.w);
        sts16(sb + (m4 + 0) * ROWB + k * 2, *reinterpret_cast<unsigned short*>(&h0));
        sts16(sb + (m4 + 1) * ROWB + k * 2, *reinterpret_cast<unsigned short*>(&h1));
        sts16(sb + (m4 + 2) * ROWB + k * 2, *reinterpret_cast<unsigned short*>(&h2));
        sts16(sb + (m4 + 3) * ROWB + k * 2, *reinterpret_cast<unsigned short*>(&h3));
    }
}
// src [k][m] bf16 (m contiguous): tile[m][k] = src[k*ld + m]
__device__ __forceinline__ void ld_tr_bf16(uint32_t sb, const unsigned short* __restrict__ src,
                                           int ld, int tid) {
#pragma unroll
    for (int i = 0; i < 4; i++) {
        int f = tid + i * 256;
        int k = f >> 5, m4 = (f & 31) << 2;
        uint2 v = *reinterpret_cast<const uint2*>(src + (size_t)k * ld + m4);
        sts16(sb + (m4 + 0) * ROWB + k * 2, (unsigned short)(v.x & 0xffff));
        sts16(sb + (m4 + 1) * ROWB + k * 2, (unsigned short)(v.x >> 16));
        sts16(sb + (m4 + 2) * ROWB + k * 2, (unsigned short)(v.y & 0xffff));
        sts16(sb + (m4 + 3) * ROWB + k * 2, (unsigned short)(v.y >> 16));
    }
}

// ---------------- generic 128x128 HMMA GEMM body ----------------
// D[m][n] = sum_k A[m][k] * B[n][k]; warp grid 4x2, warp tile 32(m) x 64(n).
// fe(row, col, v0, v1): handle D[row][col], D[row][col+1] (row,col in tile coords)
template <class FA, class FB, class FE>
__device__ __forceinline__ void gemm_body(int ktiles, FA fa, FB fb, FE fe) {
    __shared__ __align__(16) unsigned short As[128 * ROWH];
    __shared__ __align__(16) unsigned short Bs[128 * ROWH];
    const int tid = threadIdx.x, wid = tid >> 5, lane = tid & 31;
    const int wm = (wid & 3) * 32, wn = (wid >> 2) * 64;
    const uint32_t aS = smem_u32(As), bS = smem_u32(Bs);

    float acc[2][8][4];
#pragma unroll
    for (int mt = 0; mt < 2; mt++)
#pragma unroll
        for (int nt = 0; nt < 8; nt++)
#pragma unroll
            for (int j = 0; j < 4; j++) acc[mt][nt][j] = 0.f;

    for (int kt = 0; kt < ktiles; kt++) {
        fa(aS, kt);
        fb(bS, kt);
        __syncthreads();
#pragma unroll
        for (int ks = 0; ks < 2; ks++) {
            uint32_t a[2][4];
#pragma unroll
            for (int mt = 0; mt < 2; mt++) {
                uint32_t addr = aS + (wm + mt * 16 + (lane & 15)) * ROWB
                              + (ks * 16 + ((lane >> 4) << 3)) * 2;
                ldmatrix_x4(a[mt], addr);
            }
            uint32_t b[8][2];
#pragma unroll
            for (int np = 0; np < 4; np++) {
                uint32_t r[4];
                int row = wn + np * 16 + ((lane >> 4) << 3) + (lane & 7);
                int koff = ks * 16 + (((lane >> 3) & 1) << 3);
                ldmatrix_x4(r, bS + row * ROWB + koff * 2);
                b[2 * np][0] = r[0]; b[2 * np][1] = r[1];
                b[2 * np + 1][0] = r[2]; b[2 * np + 1][1] = r[3];
            }
#pragma unroll
            for (int mt = 0; mt < 2; mt++)
#pragma unroll
                for (int nt = 0; nt < 8; nt++)
                    mma16816(acc[mt][nt], a[mt], b[nt]);
        }
        __syncthreads();
    }

    // epilogue: fragment layout m16n8: rows lane>>2 (+8), cols (lane&3)*2 (+1)
#pragma unroll
    for (int mt = 0; mt < 2; mt++) {
        int r0 = wm + mt * 16 + (lane >> 2);
#pragma unroll
        for (int nt = 0; nt < 8; nt++) {
            int c = wn + nt * 8 + ((lane & 3) << 1);
            fe(r0, c, acc[mt][nt][0], acc[mt][nt][1]);
            fe(r0 + 8, c, acc[mt][nt][2], acc[mt][nt][3]);
        }
    }
}

__device__ __forceinline__ void st_bf16x2(unsigned short* dst, float v0, float v1) {
    __nv_bfloat162 h = __floats2bfloat162_rn(v0, v1);
    *reinterpret_cast<uint32_t*>(dst) = *reinterpret_cast<uint32_t*>(&h);
}

// ---------------- Stage 1a: K/Q projections -> [n][co] ----------------
// D[n][co] = sum_ci X[ci][n] * W[co][ci] + bias[co]
__global__ __launch_bounds__(256)
void proj_nt_kernel(const float* __restrict__ x, const float* __restrict__ query,
                    const float* __restrict__ kw, const float* __restrict__ kb,
                    const float* __restrict__ qw, const float* __restrict__ qb) {
    int z = blockIdx.z, b = z >> 1, which = z & 1;
    const float* X = (which ? query : x) + (size_t)b * CI * NN;
    const float* W = which ? qw : kw;
    const float* bias = which ? qb : kb;
    unsigned short* out = (which ? g_Qt : g_Kt) + (size_t)b * NN * CO;
    int n0 = blockIdx.y * 128, co0 = blockIdx.x * 128;
    int tid = threadIdx.x;

    gemm_body(CI / BK,
        [&](uint32_t s, int kt) { ld_tr_f32(s, X + (size_t)(kt * BK) * NN + n0, NN, tid); },
        [&](uint32_t s, int kt) { ld_rm_f32(s, W + (size_t)co0 * CI + kt * BK, CI, tid); },
        [&](int row, int col, float v0, float v1) {
            st_bf16x2(out + (size_t)(n0 + row) * CO + co0 + col,
                      v0 + bias[co0 + col], v1 + bias[co0 + col + 1]);
        });
}

// ---------------- Stage 1b: V projection -> [co][n] ----------------
__global__ __launch_bounds__(256)
void proj_cn_kernel(const float* __restrict__ x,
                    const float* __restrict__ vw, const float* __restrict__ vb) {
    int b = blockIdx.z;
    const float* X = x + (size_t)b * CI * NN;
    unsigned short* out = g_V + (size_t)b * CO * NN;
    int n0 = blockIdx.x * 128, co0 = blockIdx.y * 128;
    int tid = threadIdx.x;

    gemm_body(CI / BK,
        [&](uint32_t s, int kt) { ld_rm_f32(s, vw + (size_t)co0 * CI + kt * BK, CI, tid); },
        [&](uint32_t s, int kt) { ld_tr_f32(s, X + (size_t)(kt * BK) * NN + n0, NN, tid); },
        [&](int row, int col, float v0, float v1) {
            float bv = vb[co0 + row];
            st_bf16x2(out + (size_t)(co0 + row) * NN + n0 + col, v0 + bv, v1 + bv);
        });
}

// ---------------- Stage 2: S[n][m] = (1/16) sum_c Kt[n][c] * Qt[m][c] ----------------
__global__ __launch_bounds__(256)
void qk_kernel() {
    int b = blockIdx.z;
    const unsigned short* Kt = g_Kt + (size_t)b * NN * CO;
    const unsigned short* Qt = g_Qt + (size_t)b * NN * CO;
    unsigned short* S = g_S + (size_t)b * NN * NN;
    int m0 = blockIdx.x * 128, n0 = blockIdx.y * 128;
    int tid = threadIdx.x;

    gemm_body(CO / BK,
        [&](uint32_t s, int kt) { ld_rm_bf16(s, Kt + (size_t)n0 * CO + kt * BK, CO, tid); },
        [&](uint32_t s, int kt) { ld_rm_bf16(s, Qt + (size_t)m0 * CO + kt * BK, CO, tid); },
        [&](int row, int col, float v0, float v1) {
            st_bf16x2(S + (size_t)(n0 + row) * NN + m0 + col, v0 * 0.0625f, v1 * 0.0625f);
        });
}

// ---------------- Stage 3: in-place row softmax (bf16) ----------------
__global__ __launch_bounds__(256)
void softmax_kernel() {
    unsigned short* p = g_S + (size_t)blockIdx.x * NN;
    int tid = threadIdx.x;
    __shared__ float sh[9];

    uint4 u = *reinterpret_cast<uint4*>(p + tid * 8);
    float v[8];
    {
        __nv_bfloat162* hb = reinterpret_cast<__nv_bfloat162*>(&u);
#pragma unroll
        for (int i = 0; i < 4; i++) {
            float2 f = __bfloat1622float2(hb[i]);
            v[2 * i] = f.x; v[2 * i + 1] = f.y;
        }
    }
    float m = v[0];
#pragma unroll
    for (int i = 1; i < 8; i++) m = fmaxf(m, v[i]);
#pragma unroll
    for (int o = 16; o > 0; o >>= 1) m = fmaxf(m, __shfl_xor_sync(0xffffffffu, m, o));
    if ((tid & 31) == 0) sh[tid >> 5] = m;
    __syncthreads();
    if (tid == 0) {
        float r = sh[0];
#pragma unroll
        for (int i = 1; i < 8; i++) r = fmaxf(r, sh[i]);
        sh[8] = r;
    }
    __syncthreads();
    m = sh[8];

    float s = 0.f;
#pragma unroll
    for (int i = 0; i < 8; i++) { v[i] = __expf(v[i] - m); s += v[i]; }
#pragma unroll
    for (int o = 16; o > 0; o >>= 1) s += __shfl_xor_sync(0xffffffffu, s, o);
    __syncthreads();
    if ((tid & 31) == 0) sh[tid >> 5] = s;
    __syncthreads();
    if (tid == 0) {
        float r = sh[0];
#pragma unroll
        for (int i = 1; i < 8; i++) r += sh[i];
        sh[8] = r;
    }
    __syncthreads();
    float inv = 1.0f / sh[8];

    uint4 o;
    __nv_bfloat162* ob = reinterpret_cast<__nv_bfloat162*>(&o);
#pragma unroll
    for (int i = 0; i < 4; i++)
        ob[i] = __floats2bfloat162_rn(v[2 * i] * inv, v[2 * i + 1] * inv);
    *reinterpret_cast<uint4*>(p + tid * 8) = o;
}

// ---------------- Stage 4: O[n][c] = sum_m P[n][m] * V[c][m] ----------------
__global__ __launch_bounds__(256)
void av_kernel() {
    int b = blockIdx.z;
    const unsigned short* P = g_S + (size_t)b * NN * NN;
    const unsigned short* V = g_V + (size_t)b * CO * NN;
    unsigned short* O = g_O + (size_t)b * NN * CO;
    int c0 = blockIdx.x * 128, n0 = blockIdx.y * 128;
    int tid = threadIdx.x;

    gemm_body(NN / BK,
        [&](uint32_t s, int kt) { ld_rm_bf16(s, P + (size_t)n0 * NN + kt * BK, NN, tid); },
        [&](uint32_t s, int kt) { ld_rm_bf16(s, V + (size_t)c0 * NN + kt * BK, NN, tid); },
        [&](int row, int col, float v0, float v1) {
            st_bf16x2(O + (size_t)(n0 + row) * CO + c0 + col, v0, v1);
        });
}

// ---------------- Stage 5: up-proj + residual ----------------
// Raw .view: O flat [n][co] == O2[co2][n2] (ld = NN).
// out[ci][n2] = x[ci][n2] + s*(sum_co2 up_w[ci][co2]*O2[co2][n2] + up_b[ci])
__global__ __launch_bounds__(256)
void up_kernel(const float* __restrict__ x, const float* __restrict__ up_w,
               const float* __restrict__ up_b, const float* __restrict__ scaling,
               float* __restrict__ outp) {
    int b = blockIdx.z;
    const unsigned short* Ob = g_O + (size_t)b * NN * CO;  // viewed [co2][n2]
    const float* X = x + (size_t)b * CI * NN;
    float* R = outp + (size_t)b * CI * NN;
    int n0 = blockIdx.x * 128, ci0 = blockIdx.y * 128;
    int tid = threadIdx.x;
    float s = *scaling;

    gemm_body(CO / BK,
        [&](uint32_t sm, int kt) { ld_rm_f32(sm, up_w + (size_t)ci0 * CO + kt * BK, CO, tid); },
        [&](uint32_t sm, int kt) { ld_tr_bf16(sm, Ob + (size_t)(kt * BK) * NN + n0, NN, tid); },
        [&](int row, int col, float v0, float v1) {
            int ci = ci0 + row;
            float bb = up_b[ci];
            const float2 xv = *reinterpret_cast<const float2*>(X + (size_t)ci * NN + n0 + col);
            float2 o;
            o.x = xv.x + s * (v0 + bb);
            o.y = xv.y + s * (v1 + bb);
            *reinterpret_cast<float2*>(R + (size_t)ci * NN + n0 + col) = o;
        });
}

// ---------------- launch ----------------
extern "C" void kernel_launch(void* const* d_in, const int* in_sizes, int n_in,
                              void* d_out, int out_size) {
    const float* x       = (const float*)d_in[0];
    const float* query   = (const float*)d_in[1];
    const float* key_w   = (const float*)d_in[2];
    const float* key_b   = (const float*)d_in[3];
    const float* val_w   = (const float*)d_in[4];
    const float* val_b   = (const float*)d_in[5];
    const float* query_w = (const float*)d_in[6];
    const float* query_b = (const float*)d_in[7];
    const float* up_w    = (const float*)d_in[8];
    const float* up_b    = (const float*)d_in[9];
    const float* scaling = (const float*)d_in[10];
    float* out = (float*)d_out;

    proj_nt_kernel<<<dim3(CO / 128, NN / 128, Bsz * 2), 256>>>(x, query, key_w, key_b,
                                                               query_w, query_b);
    proj_cn_kernel<<<dim3(NN / 128, CO / 128, Bsz), 256>>>(x, val_w, val_b);
    qk_kernel<<<dim3(NN / 128, NN / 128, Bsz), 256>>>();
    softmax_kernel<<<dim3(Bsz * NN), 256>>>();
    av_kernel<<<dim3(CO / 128, NN / 128, Bsz), 256>>>();
    up_kernel<<<dim3(NN / 128, CI / 128, Bsz), 256>>>(x, up_w, up_b, scaling, out);
}

// round 4
// speedup vs baseline: 4.4155x; 2.2325x over previous
#include <cuda_runtime.h>
#include <cuda_bf16.h>
#include <cstdint>

#define Bsz 8
#define CI  512
#define CO  256
#define NN  2048

// ---------------- scratch (device globals, bf16) ----------------
__device__ unsigned short g_Xt[(size_t)Bsz * NN * CI];  // [b][n][ci]
__device__ unsigned short g_Qx[(size_t)Bsz * NN * CI];  // [b][n][ci] (query input)
__device__ unsigned short g_Wk[CO * CI];
__device__ unsigned short g_Wq[CO * CI];
__device__ unsigned short g_Wv[CO * CI];
__device__ unsigned short g_Wu[CI * CO];
__device__ unsigned short g_Kt[(size_t)Bsz * NN * CO];  // [b][n][co], pre-scaled by 1/16
__device__ unsigned short g_Qt[(size_t)Bsz * NN * CO];  // [b][n][co]
__device__ unsigned short g_V [(size_t)Bsz * CO * NN];  // [b][co][n]
__device__ unsigned short g_S [(size_t)Bsz * NN * NN];  // [b][n][m] logits -> probs
__device__ unsigned short g_O [(size_t)Bsz * NN * CO];  // [b][n][co]; raw view == [co2][n2]
__device__ unsigned short g_Ot[(size_t)Bsz * NN * CO];  // [b][n2][co2] (transposed view)

// ---------------- helpers ----------------
__device__ __forceinline__ uint32_t smem_u32(const void* p) {
    uint32_t a;
    asm("{ .reg .u64 t; cvta.to.shared.u64 t, %1; cvt.u32.u64 %0, t; }" : "=r"(a) : "l"(p));
    return a;
}
__device__ __forceinline__ void ldmatrix_x4(uint32_t* r, uint32_t addr) {
    asm volatile("ldmatrix.sync.aligned.m8n8.x4.shared.b16 {%0,%1,%2,%3}, [%4];"
                 : "=r"(r[0]), "=r"(r[1]), "=r"(r[2]), "=r"(r[3]) : "r"(addr));
}
__device__ __forceinline__ void mma16816(float* d, const uint32_t* a, const uint32_t* b) {
    asm volatile(
        "mma.sync.aligned.m16n8k16.row.col.f32.bf16.bf16.f32 "
        "{%0,%1,%2,%3}, {%4,%5,%6,%7}, {%8,%9}, {%0,%1,%2,%3};"
        : "+f"(d[0]), "+f"(d[1]), "+f"(d[2]), "+f"(d[3])
        : "r"(a[0]), "r"(a[1]), "r"(a[2]), "r"(a[3]), "r"(b[0]), "r"(b[1]));
}
__device__ __forceinline__ void st_bf16x2(unsigned short* dst, float v0, float v1) {
    __nv_bfloat162 h = __floats2bfloat162_rn(v0, v1);
    *reinterpret_cast<uint32_t*>(dst) = *reinterpret_cast<uint32_t*>(&h);
}

// smem tile: 128 rows x 32 halves (BK), padded to 40 halves = 80 B/row (5x16B, cp.async ok)
#define BK   32
#define ROWH 40
#define ROWB 80

// 128x32 bf16 tile via cp.async: 512 16-byte chunks, 2 per thread
__device__ __forceinline__ void cp_tile(uint32_t sb, const unsigned short* __restrict__ src,
                                        int ld, int tid) {
#pragma unroll
    for (int i = 0; i < 2; i++) {
        int ch = tid + i * 256;
        int row = ch >> 2, c = ch & 3;
        uint32_t sa = sb + row * ROWB + c * 16;
        const void* ga = src + (size_t)row * ld + c * 8;
        asm volatile("cp.async.cg.shared.global [%0], [%1], 16;" :: "r"(sa), "l"(ga));
    }
}

// ---------------- pipelined 128x128 HMMA GEMM body ----------------
// D[m][n] = sum_k A[m][k] * B[n][k]; A,B row-major bf16, k contiguous.
// warp grid 4x2, warp tile 32(m) x 64(n). fe(row, col, v0, v1) handles D pairs.
template <class FE>
__device__ __forceinline__ void gemm_body(int ktiles,
        const unsigned short* __restrict__ Ag, int lda,
        const unsigned short* __restrict__ Bg, int ldb, FE fe) {
    __shared__ __align__(16) unsigned short As[2][128 * ROWH];
    __shared__ __align__(16) unsigned short Bs[2][128 * ROWH];
    const int tid = threadIdx.x, wid = tid >> 5, lane = tid & 31;
    const int wm = (wid & 3) * 32, wn = (wid >> 2) * 64;

    float acc[2][8][4];
#pragma unroll
    for (int mt = 0; mt < 2; mt++)
#pragma unroll
        for (int nt = 0; nt < 8; nt++)
#pragma unroll
            for (int j = 0; j < 4; j++) acc[mt][nt][j] = 0.f;

    cp_tile(smem_u32(As[0]), Ag, lda, tid);
    cp_tile(smem_u32(Bs[0]), Bg, ldb, tid);
    asm volatile("cp.async.commit_group;" ::: "memory");

    for (int kt = 0; kt < ktiles; kt++) {
        int cur = kt & 1;
        if (kt + 1 < ktiles) {
            cp_tile(smem_u32(As[cur ^ 1]), Ag + (size_t)(kt + 1) * BK, lda, tid);
            cp_tile(smem_u32(Bs[cur ^ 1]), Bg + (size_t)(kt + 1) * BK, ldb, tid);
            asm volatile("cp.async.commit_group;" ::: "memory");
            asm volatile("cp.async.wait_group 1;" ::: "memory");
        } else {
            asm volatile("cp.async.wait_group 0;" ::: "memory");
        }
        __syncthreads();

        const uint32_t aB = smem_u32(As[cur]), bB = smem_u32(Bs[cur]);
#pragma unroll
        for (int ks = 0; ks < 2; ks++) {
            uint32_t a[2][4];
#pragma unroll
            for (int mt = 0; mt < 2; mt++) {
                uint32_t addr = aB + (wm + mt * 16 + (lane & 15)) * ROWB
                              + (ks * 16 + ((lane >> 4) << 3)) * 2;
                ldmatrix_x4(a[mt], addr);
            }
            uint32_t b[8][2];
#pragma unroll
            for (int np = 0; np < 4; np++) {
                uint32_t r[4];
                int row = wn + np * 16 + ((lane >> 4) << 3) + (lane & 7);
                int koff = ks * 16 + (((lane >> 3) & 1) << 3);
                ldmatrix_x4(r, bB + row * ROWB + koff * 2);
                b[2 * np][0] = r[0]; b[2 * np][1] = r[1];
                b[2 * np + 1][0] = r[2]; b[2 * np + 1][1] = r[3];
            }
#pragma unroll
            for (int mt = 0; mt < 2; mt++)
#pragma unroll
                for (int nt = 0; nt < 8; nt++)
                    mma16816(acc[mt][nt], a[mt], b[nt]);
        }
        __syncthreads();
    }

#pragma unroll
    for (int mt = 0; mt < 2; mt++) {
        int r0 = wm + mt * 16 + (lane >> 2);
#pragma unroll
        for (int nt = 0; nt < 8; nt++) {
            int c = wn + nt * 8 + ((lane & 3) << 1);
            fe(r0, c, acc[mt][nt][0], acc[mt][nt][1]);
            fe(r0 + 8, c, acc[mt][nt][2], acc[mt][nt][3]);
        }
    }
}

// ---------------- pre-pass: weights -> bf16 ----------------
__global__ __launch_bounds__(256)
void cvt_w(const float* __restrict__ kw, const float* __restrict__ qw,
           const float* __restrict__ vw, const float* __restrict__ uw) {
    int idx = blockIdx.x * 256 + threadIdx.x;           // 4 * 131072 total
    int seg = idx >> 17, off = idx & 131071;
    const float* src = seg == 0 ? kw : seg == 1 ? qw : seg == 2 ? vw : uw;
    unsigned short* dst = seg == 0 ? g_Wk : seg == 1 ? g_Wq : seg == 2 ? g_Wv : g_Wu;
    __nv_bfloat16 h = __float2bfloat16(src[off]);
    dst[off] = *reinterpret_cast<unsigned short*>(&h);
}

// ---------------- pre-pass: x / query [ci][n] fp32 -> [n][ci] bf16 ----------------
__global__ __launch_bounds__(256)
void transpose_in(const float* __restrict__ x, const float* __restrict__ query) {
    int z = blockIdx.z, b = z >> 1, which = z & 1;
    const float* src = (which ? query : x) + (size_t)b * CI * NN;
    unsigned short* dst = (which ? g_Qx : g_Xt) + (size_t)b * NN * CI;
    __shared__ unsigned short t[32][33];
    int n0 = blockIdx.x * 32, c0 = blockIdx.y * 32;
    int tx = threadIdx.x & 31, ty = threadIdx.x >> 5;   // 32x8
#pragma unroll
    for (int j = 0; j < 4; j++) {
        int ci = c0 + ty + j * 8;
        __nv_bfloat16 h = __float2bfloat16(src[(size_t)ci * NN + n0 + tx]);
        t[ty + j * 8][tx] = *reinterpret_cast<unsigned short*>(&h);
    }
    __syncthreads();
#pragma unroll
    for (int j = 0; j < 4; j++) {
        int n = n0 + ty + j * 8;
        dst[(size_t)n * CI + c0 + tx] = t[tx][ty + j * 8];
    }
}

// ---------------- mid-pass: O flat-view [co2][n2] -> Ot [n2][co2] ----------------
__global__ __launch_bounds__(256)
void transpose_o() {
    int b = blockIdx.z;
    const unsigned short* src = g_O + (size_t)b * NN * CO;  // [co2][n2], ld = NN
    unsigned short* dst = g_Ot + (size_t)b * NN * CO;       // [n2][co2], ld = CO
    __shared__ unsigned short t[32][33];
    int n0 = blockIdx.x * 32, c0 = blockIdx.y * 32;
    int tx = threadIdx.x & 31, ty = threadIdx.x >> 5;
#pragma unroll
    for (int j = 0; j < 4; j++)
        t[ty + j * 8][tx] = src[(size_t)(c0 + ty + j * 8) * NN + n0 + tx];
    __syncthreads();
#pragma unroll
    for (int j = 0; j < 4; j++)
        dst[(size_t)(n0 + ty + j * 8) * CO + c0 + tx] = t[tx][ty + j * 8];
}

// ---------------- Stage 1a: K/Q projections -> [n][co] ----------------
// D[n][co] = sum_ci Xt[n][ci] * W[co][ci] + bias[co]; K pre-scaled by 1/16
__global__ __launch_bounds__(256)
void proj_nt_kernel(const float* __restrict__ kb, const float* __restrict__ qb) {
    int z = blockIdx.z, b = z >> 1, which = z & 1;
    const unsigned short* X = (which ? g_Qx : g_Xt) + (size_t)b * NN * CI;
    const unsigned short* W = which ? g_Wq : g_Wk;
    const float* bias = which ? qb : kb;
    unsigned short* out = (which ? g_Qt : g_Kt) + (size_t)b * NN * CO;
    int n0 = blockIdx.y * 128, co0 = blockIdx.x * 128;
    float scale = which ? 1.0f : 0.0625f;

    gemm_body(CI / BK, X + (size_t)n0 * CI, CI, W + (size_t)co0 * CI, CI,
        [&](int row, int col, float v0, float v1) {
            st_bf16x2(out + (size_t)(n0 + row) * CO + co0 + col,
                      (v0 + bias[co0 + col]) * scale, (v1 + bias[co0 + col + 1]) * scale);
        });
}

// ---------------- Stage 1b: V projection -> [co][n] ----------------
__global__ __launch_bounds__(256)
void proj_cn_kernel(const float* __restrict__ vb) {
    int b = blockIdx.z;
    const unsigned short* X = g_Xt + (size_t)b * NN * CI;
    unsigned short* out = g_V + (size_t)b * CO * NN;
    int n0 = blockIdx.x * 128, co0 = blockIdx.y * 128;

    gemm_body(CI / BK, g_Wv + (size_t)co0 * CI, CI, X + (size_t)n0 * CI, CI,
        [&](int row, int col, float v0, float v1) {
            float bv = vb[co0 + row];
            st_bf16x2(out + (size_t)(co0 + row) * NN + n0 + col, v0 + bv, v1 + bv);
        });
}

// ---------------- Stage 2: S[n][m] = sum_c Kt[n][c] * Qt[m][c] (scale folded) ----------------
__global__ __launch_bounds__(256)
void qk_kernel() {
    int b = blockIdx.z;
    const unsigned short* Kt = g_Kt + (size_t)b * NN * CO;
    const unsigned short* Qt = g_Qt + (size_t)b * NN * CO;
    unsigned short* S = g_S + (size_t)b * NN * NN;
    int m0 = blockIdx.x * 128, n0 = blockIdx.y * 128;

    gemm_body(CO / BK, Kt + (size_t)n0 * CO, CO, Qt + (size_t)m0 * CO, CO,
        [&](int row, int col, float v0, float v1) {
            st_bf16x2(S + (size_t)(n0 + row) * NN + m0 + col, v0, v1);
        });
}

// ---------------- Stage 3: in-place row softmax (bf16) ----------------
__global__ __launch_bounds__(256)
void softmax_kernel() {
    unsigned short* p = g_S + (size_t)blockIdx.x * NN;
    int tid = threadIdx.x;
    __shared__ float sh[9];

    uint4 u = *reinterpret_cast<uint4*>(p + tid * 8);
    float v[8];
    {
        __nv_bfloat162* hb = reinterpret_cast<__nv_bfloat162*>(&u);
#pragma unroll
        for (int i = 0; i < 4; i++) {
            float2 f = __bfloat1622float2(hb[i]);
            v[2 * i] = f.x; v[2 * i + 1] = f.y;
        }
    }
    float m = v[0];
#pragma unroll
    for (int i = 1; i < 8; i++) m = fmaxf(m, v[i]);
#pragma unroll
    for (int o = 16; o > 0; o >>= 1) m = fmaxf(m, __shfl_xor_sync(0xffffffffu, m, o));
    if ((tid & 31) == 0) sh[tid >> 5] = m;
    __syncthreads();
    if (tid == 0) {
        float r = sh[0];
#pragma unroll
        for (int i = 1; i < 8; i++) r = fmaxf(r, sh[i]);
        sh[8] = r;
    }
    __syncthreads();
    m = sh[8];

    float s = 0.f;
#pragma unroll
    for (int i = 0; i < 8; i++) { v[i] = __expf(v[i] - m); s += v[i]; }
#pragma unroll
    for (int o = 16; o > 0; o >>= 1) s += __shfl_xor_sync(0xffffffffu, s, o);
    __syncthreads();
    if ((tid & 31) == 0) sh[tid >> 5] = s;
    __syncthreads();
    if (tid == 0) {
        float r = sh[0];
#pragma unroll
        for (int i = 1; i < 8; i++) r += sh[i];
        sh[8] = r;
    }
    __syncthreads();
    float inv = 1.0f / sh[8];

    uint4 o;
    __nv_bfloat162* ob = reinterpret_cast<__nv_bfloat162*>(&o);
#pragma unroll
    for (int i = 0; i < 4; i++)
        ob[i] = __floats2bfloat162_rn(v[2 * i] * inv, v[2 * i + 1] * inv);
    *reinterpret_cast<uint4*>(p + tid * 8) = o;
}

// ---------------- Stage 4: O[n][c] = sum_m P[n][m] * V[c][m] ----------------
__global__ __launch_bounds__(256)
void av_kernel() {
    int b = blockIdx.z;
    const unsigned short* P = g_S + (size_t)b * NN * NN;
    const unsigned short* V = g_V + (size_t)b * CO * NN;
    unsigned short* O = g_O + (size_t)b * NN * CO;
    int c0 = blockIdx.x * 128, n0 = blockIdx.y * 128;

    gemm_body(NN / BK, P + (size_t)n0 * NN, NN, V + (size_t)c0 * NN, NN,
        [&](int row, int col, float v0, float v1) {
            st_bf16x2(O + (size_t)(n0 + row) * CO + c0 + col, v0, v1);
        });
}

// ---------------- Stage 5: up-proj + residual ----------------
// out[ci][n2] = x[ci][n2] + s*(sum_co2 up_w[ci][co2]*Ot[n2][co2] + up_b[ci])
__global__ __launch_bounds__(256)
void up_kernel(const float* __restrict__ x, const float* __restrict__ up_b,
               const float* __restrict__ scaling, float* __restrict__ outp) {
    int b = blockIdx.z;
    const unsigned short* Ot = g_Ot + (size_t)b * NN * CO;
    const float* X = x + (size_t)b * CI * NN;
    float* R = outp + (size_t)b * CI * NN;
    int n0 = blockIdx.x * 128, ci0 = blockIdx.y * 128;
    float s = *scaling;

    gemm_body(CO / BK, g_Wu + (size_t)ci0 * CO, CO, Ot + (size_t)n0 * CO, CO,
        [&](int row, int col, float v0, float v1) {
            int ci = ci0 + row;
            float bb = up_b[ci];
            const float2 xv = *reinterpret_cast<const float2*>(X + (size_t)ci * NN + n0 + col);
            float2 o;
            o.x = xv.x + s * (v0 + bb);
            o.y = xv.y + s * (v1 + bb);
            *reinterpret_cast<float2*>(R + (size_t)ci * NN + n0 + col) = o;
        });
}

// ---------------- launch ----------------
extern "C" void kernel_launch(void* const* d_in, const int* in_sizes, int n_in,
                              void* d_out, int out_size) {
    const float* x       = (const float*)d_in[0];
    const float* query   = (const float*)d_in[1];
    const float* key_w   = (const float*)d_in[2];
    const float* key_b   = (const float*)d_in[3];
    const float* val_w   = (const float*)d_in[4];
    const float* val_b   = (const float*)d_in[5];
    const float* query_w = (const float*)d_in[6];
    const float* query_b = (const float*)d_in[7];
    const float* up_w    = (const float*)d_in[8];
    const float* up_b    = (const float*)d_in[9];
    const float* scaling = (const float*)d_in[10];
    float* out = (float*)d_out;

    cvt_w<<<2048, 256>>>(key_w, query_w, val_w, up_w);
    transpose_in<<<dim3(NN / 32, CI / 32, Bsz * 2), 256>>>(x, query);
    proj_nt_kernel<<<dim3(CO / 128, NN / 128, Bsz * 2), 256>>>(key_b, query_b);
    proj_cn_kernel<<<dim3(NN / 128, CO / 128, Bsz), 256>>>(val_b);
    qk_kernel<<<dim3(NN / 128, NN / 128, Bsz), 256>>>();
    softmax_kernel<<<dim3(Bsz * NN), 256>>>();
    av_kernel<<<dim3(CO / 128, NN / 128, Bsz), 256>>>();
    transpose_o<<<dim3(NN / 32, CO / 32, Bsz), 256>>>();
    up_kernel<<<dim3(NN / 128, CI / 128, Bsz), 256>>>(x, up_b, scaling, out);
}

// round 5
// speedup vs baseline: 4.5036x; 1.0200x over previous
#include <cuda_runtime.h>
#include <cuda_bf16.h>
#include <cstdint>

#define Bsz 8
#define CI  512
#define CO  256
#define NN  2048

// ---------------- scratch (device globals, bf16) ----------------
__device__ unsigned short g_Xt[(size_t)Bsz * NN * CI];  // [b][n][ci]
__device__ unsigned short g_Qx[(size_t)Bsz * NN * CI];  // [b][n][ci] (query input)
__device__ unsigned short g_Wk[CO * CI];
__device__ unsigned short g_Wq[CO * CI];
__device__ unsigned short g_Wv[CO * CI];
__device__ unsigned short g_Wu[CI * CO];
__device__ unsigned short g_Kt[(size_t)Bsz * NN * CO];  // [b][n][co], pre-scaled 1/16
__device__ unsigned short g_Qt[(size_t)Bsz * NN * CO];  // [b][n][co]
__device__ unsigned short g_V [(size_t)Bsz * CO * NN];  // [b][co][n]
__device__ unsigned short g_S [(size_t)Bsz * NN * NN];  // [b][n][m] exp(logits), unnormalized
__device__ unsigned short g_O [(size_t)Bsz * NN * CO];  // [b][n][co]; raw view == [co2][n2]
__device__ unsigned short g_Ot[(size_t)Bsz * NN * CO];  // [b][n2][co2]
__device__ float          g_rowsum[(size_t)Bsz * NN];   // softmax denominators

// ---------------- helpers ----------------
__device__ __forceinline__ uint32_t smem_u32(const void* p) {
    uint32_t a;
    asm("{ .reg .u64 t; cvta.to.shared.u64 t, %1; cvt.u32.u64 %0, t; }" : "=r"(a) : "l"(p));
    return a;
}
__device__ __forceinline__ void ldmatrix_x4(uint32_t* r, uint32_t addr) {
    asm volatile("ldmatrix.sync.aligned.m8n8.x4.shared.b16 {%0,%1,%2,%3}, [%4];"
                 : "=r"(r[0]), "=r"(r[1]), "=r"(r[2]), "=r"(r[3]) : "r"(addr));
}
__device__ __forceinline__ void mma16816(float* d, const uint32_t* a, const uint32_t* b) {
    asm volatile(
        "mma.sync.aligned.m16n8k16.row.col.f32.bf16.bf16.f32 "
        "{%0,%1,%2,%3}, {%4,%5,%6,%7}, {%8,%9}, {%0,%1,%2,%3};"
        : "+f"(d[0]), "+f"(d[1]), "+f"(d[2]), "+f"(d[3])
        : "r"(a[0]), "r"(a[1]), "r"(a[2]), "r"(a[3]), "r"(b[0]), "r"(b[1]));
}
__device__ __forceinline__ void st_bf16x2(unsigned short* dst, float v0, float v1) {
    __nv_bfloat162 h = __floats2bfloat162_rn(v0, v1);
    *reinterpret_cast<uint32_t*>(dst) = *reinterpret_cast<uint32_t*>(&h);
}

// smem tile: 128 rows x 32 halves (BK), padded to 40 halves = 80 B/row
#define BK   32
#define ROWB 80
#define STAGE_H 10240            // halves per stage (A tile 5120 + B tile 5120)
#define SMEM_BYTES (4 * STAGE_H * 2)

// 128x32 bf16 tile via cp.async: 512 16-byte chunks, 2 per thread
__device__ __forceinline__ void cp_tile(uint32_t sb, const unsigned short* __restrict__ src,
                                        int ld, int tid) {
#pragma unroll
    for (int i = 0; i < 2; i++) {
        int ch = tid + i * 256;
        int row = ch >> 2, c = ch & 3;
        uint32_t sa = sb + row * ROWB + c * 16;
        const void* ga = src + (size_t)row * ld + c * 8;
        asm volatile("cp.async.cg.shared.global [%0], [%1], 16;" :: "r"(sa), "l"(ga));
    }
}

// ---------------- 4-stage pipelined 128x128 HMMA GEMM ----------------
// D[m][n] = sum_k A[m][k] * B[n][k]; A,B row-major bf16.
// warp grid 4x2, warp tile 32(m) x 64(n).
// fe(r0, col, v): v = {D[r0][col], D[r0][col+1], D[r0+8][col], D[r0+8][col+1]}
template <class FE>
__device__ __forceinline__ void gemm_body(int ktiles,
        const unsigned short* __restrict__ Ag, int lda,
        const unsigned short* __restrict__ Bg, int ldb, FE fe) {
    extern __shared__ __align__(16) unsigned short sm[];
    const int tid = threadIdx.x, wid = tid >> 5, lane = tid & 31;
    const int wm = (wid & 3) * 32, wn = (wid >> 2) * 64;

    float acc[2][8][4];
#pragma unroll
    for (int mt = 0; mt < 2; mt++)
#pragma unroll
        for (int nt = 0; nt < 8; nt++)
#pragma unroll
            for (int j = 0; j < 4; j++) acc[mt][nt][j] = 0.f;

#pragma unroll
    for (int s = 0; s < 3; s++) {
        uint32_t sb = smem_u32(sm + s * STAGE_H);
        cp_tile(sb, Ag + (size_t)s * BK, lda, tid);
        cp_tile(sb + 10240, Bg + (size_t)s * BK, ldb, tid);
        asm volatile("cp.async.commit_group;" ::: "memory");
    }

    for (int kt = 0; kt < ktiles; kt++) {
        if (kt < ktiles - 2)       asm volatile("cp.async.wait_group 2;" ::: "memory");
        else if (kt == ktiles - 2) asm volatile("cp.async.wait_group 1;" ::: "memory");
        else                       asm volatile("cp.async.wait_group 0;" ::: "memory");
        __syncthreads();

        if (kt + 3 < ktiles) {
            uint32_t sb = smem_u32(sm + ((kt + 3) & 3) * STAGE_H);
            cp_tile(sb, Ag + (size_t)(kt + 3) * BK, lda, tid);
            cp_tile(sb + 10240, Bg + (size_t)(kt + 3) * BK, ldb, tid);
            asm volatile("cp.async.commit_group;" ::: "memory");
        }

        const uint32_t aB = smem_u32(sm + (kt & 3) * STAGE_H);
        const uint32_t bB = aB + 10240;
#pragma unroll
        for (int ks = 0; ks < 2; ks++) {
            uint32_t a[2][4];
#pragma unroll
            for (int mt = 0; mt < 2; mt++) {
                uint32_t addr = aB + (wm + mt * 16 + (lane & 15)) * ROWB
                              + (ks * 16 + ((lane >> 4) << 3)) * 2;
                ldmatrix_x4(a[mt], addr);
            }
            uint32_t b[8][2];
#pragma unroll
            for (int np = 0; np < 4; np++) {
                uint32_t r[4];
                int row = wn + np * 16 + ((lane >> 4) << 3) + (lane & 7);
                int koff = ks * 16 + (((lane >> 3) & 1) << 3);
                ldmatrix_x4(r, bB + row * ROWB + koff * 2);
                b[2 * np][0] = r[0]; b[2 * np][1] = r[1];
                b[2 * np + 1][0] = r[2]; b[2 * np + 1][1] = r[3];
            }
#pragma unroll
            for (int mt = 0; mt < 2; mt++)
#pragma unroll
                for (int nt = 0; nt < 8; nt++)
                    mma16816(acc[mt][nt], a[mt], b[nt]);
        }
    }

#pragma unroll
    for (int mt = 0; mt < 2; mt++) {
        int r0 = wm + mt * 16 + (lane >> 2);
#pragma unroll
        for (int nt = 0; nt < 8; nt++)
            fe(r0, wn + nt * 8 + ((lane & 3) << 1), acc[mt][nt]);
    }
}

// ---------------- small pre/mid passes ----------------
__global__ __launch_bounds__(256)
void cvt_w(const float* __restrict__ kw, const float* __restrict__ qw,
           const float* __restrict__ vw, const float* __restrict__ uw) {
    int idx = blockIdx.x * 256 + threadIdx.x;
    int seg = idx >> 17, off = idx & 131071;
    const float* src = seg == 0 ? kw : seg == 1 ? qw : seg == 2 ? vw : uw;
    unsigned short* dst = seg == 0 ? g_Wk : seg == 1 ? g_Wq : seg == 2 ? g_Wv : g_Wu;
    __nv_bfloat16 h = __float2bfloat16(src[off]);
    dst[off] = *reinterpret_cast<unsigned short*>(&h);
}

__global__ __launch_bounds__(64)
void zero_rowsum() { g_rowsum[blockIdx.x * 64 + threadIdx.x] = 0.f; }

__global__ __launch_bounds__(256)
void transpose_in(const float* __restrict__ x, const float* __restrict__ query) {
    int z = blockIdx.z, b = z >> 1, which = z & 1;
    const float* src = (which ? query : x) + (size_t)b * CI * NN;
    unsigned short* dst = (which ? g_Qx : g_Xt) + (size_t)b * NN * CI;
    __shared__ unsigned short t[32][33];
    int n0 = blockIdx.x * 32, c0 = blockIdx.y * 32;
    int tx = threadIdx.x & 31, ty = threadIdx.x >> 5;
#pragma unroll
    for (int j = 0; j < 4; j++) {
        int ci = c0 + ty + j * 8;
        __nv_bfloat16 h = __float2bfloat16(src[(size_t)ci * NN + n0 + tx]);
        t[ty + j * 8][tx] = *reinterpret_cast<unsigned short*>(&h);
    }
    __syncthreads();
#pragma unroll
    for (int j = 0; j < 4; j++)
        dst[(size_t)(n0 + ty + j * 8) * CI + c0 + tx] = t[tx][ty + j * 8];
}

__global__ __launch_bounds__(256)
void transpose_o() {
    int b = blockIdx.z;
    const unsigned short* src = g_O + (size_t)b * NN * CO;  // [co2][n2], ld = NN
    unsigned short* dst = g_Ot + (size_t)b * NN * CO;       // [n2][co2], ld = CO
    __shared__ unsigned short t[32][33];
    int n0 = blockIdx.x * 32, c0 = blockIdx.y * 32;
    int tx = threadIdx.x & 31, ty = threadIdx.x >> 5;
#pragma unroll
    for (int j = 0; j < 4; j++)
        t[ty + j * 8][tx] = src[(size_t)(c0 + ty + j * 8) * NN + n0 + tx];
    __syncthreads();
#pragma unroll
    for (int j = 0; j < 4; j++)
        dst[(size_t)(n0 + ty + j * 8) * CO + c0 + tx] = t[tx][ty + j * 8];
}

// ---------------- Stage 1a: K/Q projections -> [n][co] (K pre-scaled 1/16) ----------------
__global__ __launch_bounds__(256)
void proj_nt_kernel(const float* __restrict__ kb, const float* __restrict__ qb) {
    int z = blockIdx.z, b = z >> 1, which = z & 1;
    const unsigned short* X = (which ? g_Qx : g_Xt) + (size_t)b * NN * CI;
    const unsigned short* W = which ? g_Wq : g_Wk;
    const float* bias = which ? qb : kb;
    unsigned short* out = (which ? g_Qt : g_Kt) + (size_t)b * NN * CO;
    int n0 = blockIdx.y * 128, co0 = blockIdx.x * 128;
    float scale = which ? 1.0f : 0.0625f;

    gemm_body(CI / BK, X + (size_t)n0 * CI, CI, W + (size_t)co0 * CI, CI,
        [&](int row, int col, const float* v) {
            float b0 = bias[co0 + col], b1 = bias[co0 + col + 1];
            st_bf16x2(out + (size_t)(n0 + row) * CO + co0 + col,
                      (v[0] + b0) * scale, (v[1] + b1) * scale);
            st_bf16x2(out + (size_t)(n0 + row + 8) * CO + co0 + col,
                      (v[2] + b0) * scale, (v[3] + b1) * scale);
        });
}

// ---------------- Stage 1b: V projection -> [co][n] ----------------
__global__ __launch_bounds__(256)
void proj_cn_kernel(const float* __restrict__ vb) {
    int b = blockIdx.z;
    const unsigned short* X = g_Xt + (size_t)b * NN * CI;
    unsigned short* out = g_V + (size_t)b * CO * NN;
    int n0 = blockIdx.x * 128, co0 = blockIdx.y * 128;

    gemm_body(CI / BK, g_Wv + (size_t)co0 * CI, CI, X + (size_t)n0 * CI, CI,
        [&](int row, int col, const float* v) {
            float bv0 = vb[co0 + row], bv1 = vb[co0 + row + 8];
            st_bf16x2(out + (size_t)(co0 + row) * NN + n0 + col, v[0] + bv0, v[1] + bv0);
            st_bf16x2(out + (size_t)(co0 + row + 8) * NN + n0 + col, v[2] + bv1, v[3] + bv1);
        });
}

// ---------------- Stage 2: S = exp(K.Q/16), rowsum via atomics ----------------
__global__ __launch_bounds__(256)
void qk_kernel() {
    int b = blockIdx.z;
    const unsigned short* Kt = g_Kt + (size_t)b * NN * CO;
    const unsigned short* Qt = g_Qt + (size_t)b * NN * CO;
    unsigned short* S = g_S + (size_t)b * NN * NN;
    int m0 = blockIdx.x * 128, n0 = blockIdx.y * 128;

    float rs[4] = {0.f, 0.f, 0.f, 0.f};
    gemm_body(CO / BK, Kt + (size_t)n0 * CO, CO, Qt + (size_t)m0 * CO, CO,
        [&](int row, int col, const float* v) {
            float e0 = __expf(v[0]), e1 = __expf(v[1]);
            float e2 = __expf(v[2]), e3 = __expf(v[3]);
            st_bf16x2(S + (size_t)(n0 + row) * NN + m0 + col, e0, e1);
            st_bf16x2(S + (size_t)(n0 + row + 8) * NN + m0 + col, e2, e3);
            rs[(row >> 3) & 3] += e0 + e1;        // idx = 2*mt
            rs[((row >> 3) & 3) | 1] += e2 + e3;  // idx = 2*mt+1
        });

    int lane = threadIdx.x & 31, wid = threadIdx.x >> 5;
    int wm = (wid & 3) * 32, q = lane >> 2;
#pragma unroll
    for (int i = 0; i < 4; i++) {
        float s = rs[i];
        s += __shfl_xor_sync(0xffffffffu, s, 1);
        s += __shfl_xor_sync(0xffffffffu, s, 2);
        if ((lane & 3) == 0) {
            int row = wm + (i >> 1) * 16 + (i & 1) * 8 + q;
            atomicAdd(&g_rowsum[(size_t)b * NN + n0 + row], s);
        }
    }
}

// ---------------- Stage 4: O[n][c] = (sum_m e[n][m] V[c][m]) / rowsum[n] ----------------
__global__ __launch_bounds__(256)
void av_kernel() {
    int b = blockIdx.z;
    const unsigned short* P = g_S + (size_t)b * NN * NN;
    const unsigned short* V = g_V + (size_t)b * CO * NN;
    const float* rsum = g_rowsum + (size_t)b * NN;
    unsigned short* O = g_O + (size_t)b * NN * CO;
    int c0 = blockIdx.x * 128, n0 = blockIdx.y * 128;

    gemm_body(NN / BK, P + (size_t)n0 * NN, NN, V + (size_t)c0 * NN, NN,
        [&](int row, int col, const float* v) {
            float i0 = 1.0f / rsum[n0 + row];
            float i1 = 1.0f / rsum[n0 + row + 8];
            st_bf16x2(O + (size_t)(n0 + row) * CO + c0 + col, v[0] * i0, v[1] * i0);
            st_bf16x2(O + (size_t)(n0 + row + 8) * CO + c0 + col, v[2] * i1, v[3] * i1);
        });
}

// ---------------- Stage 5: up-proj + residual ----------------
__global__ __launch_bounds__(256)
void up_kernel(const float* __restrict__ x, const float* __restrict__ up_b,
               const float* __restrict__ scaling, float* __restrict__ outp) {
    int b = blockIdx.z;
    const unsigned short* Ot = g_Ot + (size_t)b * NN * CO;
    const float* X = x + (size_t)b * CI * NN;
    float* R = outp + (size_t)b * CI * NN;
    int n0 = blockIdx.x * 128, ci0 = blockIdx.y * 128;
    float s = *scaling;

    gemm_body(CO / BK, g_Wu + (size_t)ci0 * CO, CO, Ot + (size_t)n0 * CO, CO,
        [&](int row, int col, const float* v) {
#pragma unroll
            for (int h = 0; h < 2; h++) {
                int ci = ci0 + row + h * 8;
                float bb = up_b[ci];
                const float2 xv = *reinterpret_cast<const float2*>(X + (size_t)ci * NN + n0 + col);
                float2 o;
                o.x = xv.x + s * (v[2 * h] + bb);
                o.y = xv.y + s * (v[2 * h + 1] + bb);
                *reinterpret_cast<float2*>(R + (size_t)ci * NN + n0 + col) = o;
            }
        });
}

// ---------------- launch ----------------
extern "C" void kernel_launch(void* const* d_in, const int* in_sizes, int n_in,
                              void* d_out, int out_size) {
    const float* x       = (const float*)d_in[0];
    const float* query   = (const float*)d_in[1];
    const float* key_w   = (const float*)d_in[2];
    const float* key_b   = (const float*)d_in[3];
    const float* val_w   = (const float*)d_in[4];
    const float* val_b   = (const float*)d_in[5];
    const float* query_w = (const float*)d_in[6];
    const float* query_b = (const float*)d_in[7];
    const float* up_w    = (const float*)d_in[8];
    const float* up_b    = (const float*)d_in[9];
    const float* scaling = (const float*)d_in[10];
    float* out = (float*)d_out;

    static bool attr_done = false;
    if (!attr_done) {
        cudaFuncSetAttribute(proj_nt_kernel, cudaFuncAttributeMaxDynamicSharedMemorySize, SMEM_BYTES);
        cudaFuncSetAttribute(proj_cn_kernel, cudaFuncAttributeMaxDynamicSharedMemorySize, SMEM_BYTES);
        cudaFuncSetAttribute(qk_kernel,      cudaFuncAttributeMaxDynamicSharedMemorySize, SMEM_BYTES);
        cudaFuncSetAttribute(av_kernel,      cudaFuncAttributeMaxDynamicSharedMemorySize, SMEM_BYTES);
        cudaFuncSetAttribute(up_kernel,      cudaFuncAttributeMaxDynamicSharedMemorySize, SMEM_BYTES);
        attr_done = true;
    }

    cvt_w<<<2048, 256>>>(key_w, query_w, val_w, up_w);
    zero_rowsum<<<(Bsz * NN) / 64, 64>>>();
    transpose_in<<<dim3(NN / 32, CI / 32, Bsz * 2), 256>>>(x, query);
    proj_nt_kernel<<<dim3(CO / 128, NN / 128, Bsz * 2), 256, SMEM_BYTES>>>(key_b, query_b);
    proj_cn_kernel<<<dim3(NN / 128, CO / 128, Bsz), 256, SMEM_BYTES>>>(val_b);
    qk_kernel<<<dim3(NN / 128, NN / 128, Bsz), 256, SMEM_BYTES>>>();
    av_kernel<<<dim3(CO / 128, NN / 128, Bsz), 256, SMEM_BYTES>>>();
    transpose_o<<<dim3(NN / 32, CO / 32, Bsz), 256>>>();
    up_kernel<<<dim3(NN / 128, CI / 128, Bsz), 256, SMEM_BYTES>>>(x, up_b, scaling, out);
}

// round 7
// speedup vs baseline: 5.4166x; 1.2027x over previous
#include <cuda_runtime.h>
#include <cuda_bf16.h>
#include <cstdint>

#define Bsz 8
#define CI  512
#define CO  256
#define NN  2048

// ---------------- scratch (device globals, bf16) ----------------
__device__ unsigned short g_Xt[(size_t)Bsz * NN * CI];  // [b][n][ci]
__device__ unsigned short g_Qx[(size_t)Bsz * NN * CI];  // [b][n][ci] (query input)
__device__ unsigned short g_Wk[CO * CI];
__device__ unsigned short g_Wq[CO * CI];
__device__ unsigned short g_Wv[CO * CI];
__device__ unsigned short g_Wu[CI * CO];
__device__ unsigned short g_Kt[(size_t)Bsz * NN * CO];  // [b][n][co], pre-scaled 1/16
__device__ unsigned short g_Qt[(size_t)Bsz * NN * CO];  // [b][n][co]
__device__ unsigned short g_V [(size_t)Bsz * CO * NN];  // [b][co][n]
__device__ unsigned short g_S [(size_t)Bsz * NN * NN];  // [b][n][m] exp(logits)
__device__ unsigned short g_O [(size_t)Bsz * NN * CO];  // [b][n][co]; raw view == [co2][n2]
__device__ unsigned short g_Ot[(size_t)Bsz * NN * CO];  // [b][n2][co2]
__device__ float          g_rowsum[(size_t)Bsz * NN];

// ---------------- helpers ----------------
__device__ __forceinline__ uint32_t smem_u32(const void* p) {
    uint32_t a;
    asm("{ .reg .u64 t; cvta.to.shared.u64 t, %1; cvt.u32.u64 %0, t; }" : "=r"(a) : "l"(p));
    return a;
}
__device__ __forceinline__ void ldmatrix_x4(uint32_t* r, uint32_t addr) {
    asm volatile("ldmatrix.sync.aligned.m8n8.x4.shared.b16 {%0,%1,%2,%3}, [%4];"
                 : "=r"(r[0]), "=r"(r[1]), "=r"(r[2]), "=r"(r[3]) : "r"(addr));
}
__device__ __forceinline__ void mma16816(float* d, const uint32_t* a, const uint32_t* b) {
    asm volatile(
        "mma.sync.aligned.m16n8k16.row.col.f32.bf16.bf16.f32 "
        "{%0,%1,%2,%3}, {%4,%5,%6,%7}, {%8,%9}, {%0,%1,%2,%3};"
        : "+f"(d[0]), "+f"(d[1]), "+f"(d[2]), "+f"(d[3])
        : "r"(a[0]), "r"(a[1]), "r"(a[2]), "r"(a[3]), "r"(b[0]), "r"(b[1]));
}
__device__ __forceinline__ void st_bf16x2(unsigned short* dst, float v0, float v1) {
    __nv_bfloat162 h = __floats2bfloat162_rn(v0, v1);
    *reinterpret_cast<uint32_t*>(dst) = *reinterpret_cast<uint32_t*>(&h);
}

// smem tile: 128 rows x 64 halves (BK), padded to 72 halves = 144 B/row (9x16B)
#define BK      64
#define ROWB    144
#define TILE_H  (128 * 72)            // halves per tile
#define STAGE_H (2 * TILE_H)          // A + B
#define NSTAGE  3
#define SMEM_BYTES (NSTAGE * STAGE_H * 2)   // 110592

// 128x64 bf16 tile via cp.async: 1024 16-byte chunks, 4 per thread
__device__ __forceinline__ void cp_tile(uint32_t sb, const unsigned short* __restrict__ src,
                                        int ld, int tid) {
#pragma unroll
    for (int i = 0; i < 4; i++) {
        int ch = tid + i * 256;
        int row = ch >> 3, c = ch & 7;
        uint32_t sa = sb + row * ROWB + c * 16;
        const void* ga = src + (size_t)row * ld + c * 8;
        asm volatile("cp.async.cg.shared.global [%0], [%1], 16;" :: "r"(sa), "l"(ga));
    }
}

// ---------------- 3-stage pipelined 128x128 HMMA GEMM, BK=64 ----------------
// D[m][n] = sum_k A[m][k] * B[n][k]; A,B row-major bf16.
// warp grid 4x2, warp tile 32(m) x 64(n).
// fe(r0, col, v): v = {D[r0][col], D[r0][col+1], D[r0+8][col], D[r0+8][col+1]}
template <class FE>
__device__ __forceinline__ void gemm_body(int ktiles,
        const unsigned short* __restrict__ Ag, int lda,
        const unsigned short* __restrict__ Bg, int ldb, FE fe) {
    extern __shared__ __align__(16) unsigned short sm[];
    const int tid = threadIdx.x, wid = tid >> 5, lane = tid & 31;
    const int wm = (wid & 3) * 32, wn = (wid >> 2) * 64;

    float acc[2][8][4];
#pragma unroll
    for (int mt = 0; mt < 2; mt++)
#pragma unroll
        for (int nt = 0; nt < 8; nt++)
#pragma unroll
            for (int j = 0; j < 4; j++) acc[mt][nt][j] = 0.f;

#pragma unroll
    for (int s = 0; s < 2; s++) {
        uint32_t sb = smem_u32(sm + s * STAGE_H);
        cp_tile(sb, Ag + (size_t)s * BK, lda, tid);
        cp_tile(sb + TILE_H * 2, Bg + (size_t)s * BK, ldb, tid);
        asm volatile("cp.async.commit_group;" ::: "memory");
    }

    int stage = 0;
    for (int kt = 0; kt < ktiles; kt++) {
        if (kt == ktiles - 1) asm volatile("cp.async.wait_group 0;" ::: "memory");
        else                  asm volatile("cp.async.wait_group 1;" ::: "memory");
        __syncthreads();

        if (kt + 2 < ktiles) {
            int ps = stage + 2; if (ps >= NSTAGE) ps -= NSTAGE;
            uint32_t sb = smem_u32(sm + ps * STAGE_H);
            cp_tile(sb, Ag + (size_t)(kt + 2) * BK, lda, tid);
            cp_tile(sb + TILE_H * 2, Bg + (size_t)(kt + 2) * BK, ldb, tid);
            asm volatile("cp.async.commit_group;" ::: "memory");
        }

        const uint32_t aB = smem_u32(sm + stage * STAGE_H);
        const uint32_t bB = aB + TILE_H * 2;
#pragma unroll
        for (int ks = 0; ks < 4; ks++) {
            uint32_t a[2][4];
#pragma unroll
            for (int mt = 0; mt < 2; mt++) {
                uint32_t addr = aB + (wm + mt * 16 + (lane & 15)) * ROWB
                              + (ks * 16 + ((lane >> 4) << 3)) * 2;
                ldmatrix_x4(a[mt], addr);
            }
            uint32_t b[8][2];
#pragma unroll
            for (int np = 0; np < 4; np++) {
                uint32_t r[4];
                int row = wn + np * 16 + ((lane >> 4) << 3) + (lane & 7);
                int koff = ks * 16 + (((lane >> 3) & 1) << 3);
                ldmatrix_x4(r, bB + row * ROWB + koff * 2);
                b[2 * np][0] = r[0]; b[2 * np][1] = r[1];
                b[2 * np + 1][0] = r[2]; b[2 * np + 1][1] = r[3];
            }
#pragma unroll
            for (int mt = 0; mt < 2; mt++)
#pragma unroll
                for (int nt = 0; nt < 8; nt++)
                    mma16816(acc[mt][nt], a[mt], b[nt]);
        }
        if (++stage == NSTAGE) stage = 0;
    }

#pragma unroll
    for (int mt = 0; mt < 2; mt++) {
        int r0 = wm + mt * 16 + (lane >> 2);
#pragma unroll
        for (int nt = 0; nt < 8; nt++)
            fe(r0, wn + nt * 8 + ((lane & 3) << 1), acc[mt][nt]);
    }
}

// ---------------- small pre/mid passes ----------------
__global__ __launch_bounds__(256)
void cvt_w(const float* __restrict__ kw, const float* __restrict__ qw,
           const float* __restrict__ vw, const float* __restrict__ uw) {
    int idx = blockIdx.x * 256 + threadIdx.x;
    int seg = idx >> 17, off = idx & 131071;
    const float* src = seg == 0 ? kw : seg == 1 ? qw : seg == 2 ? vw : uw;
    unsigned short* dst = seg == 0 ? g_Wk : seg == 1 ? g_Wq : seg == 2 ? g_Wv : g_Wu;
    __nv_bfloat16 h = __float2bfloat16(src[off]);
    dst[off] = *reinterpret_cast<unsigned short*>(&h);
}

__global__ __launch_bounds__(64)
void zero_rowsum() { g_rowsum[blockIdx.x * 64 + threadIdx.x] = 0.f; }

__global__ __launch_bounds__(256)
void transpose_in(const float* __restrict__ x, const float* __restrict__ query) {
    int z = blockIdx.z, b = z >> 1, which = z & 1;
    const float* src = (which ? query : x) + (size_t)b * CI * NN;
    unsigned short* dst = (which ? g_Qx : g_Xt) + (size_t)b * NN * CI;
    __shared__ unsigned short t[32][33];
    int n0 = blockIdx.x * 32, c0 = blockIdx.y * 32;
    int tx = threadIdx.x & 31, ty = threadIdx.x >> 5;
#pragma unroll
    for (int j = 0; j < 4; j++) {
        int ci = c0 + ty + j * 8;
        __nv_bfloat16 h = __float2bfloat16(src[(size_t)ci * NN + n0 + tx]);
        t[ty + j * 8][tx] = *reinterpret_cast<unsigned short*>(&h);
    }
    __syncthreads();
#pragma unroll
    for (int j = 0; j < 4; j++)
        dst[(size_t)(n0 + ty + j * 8) * CI + c0 + tx] = t[tx][ty + j * 8];
}

__global__ __launch_bounds__(256)
void transpose_o() {
    int b = blockIdx.z;
    const unsigned short* src = g_O + (size_t)b * NN * CO;  // [co2][n2], ld = NN
    unsigned short* dst = g_Ot + (size_t)b * NN * CO;       // [n2][co2], ld = CO
    __shared__ unsigned short t[32][33];
    int n0 = blockIdx.x * 32, c0 = blockIdx.y * 32;
    int tx = threadIdx.x & 31, ty = threadIdx.x >> 5;
#pragma unroll
    for (int j = 0; j < 4; j++)
        t[ty + j * 8][tx] = src[(size_t)(c0 + ty + j * 8) * NN + n0 + tx];
    __syncthreads();
#pragma unroll
    for (int j = 0; j < 4; j++)
        dst[(size_t)(n0 + ty + j * 8) * CO + c0 + tx] = t[tx][ty + j * 8];
}

// ---------------- Stage 1: ALL projections in one launch ----------------
// z = b*3 + which; which: 0=K -> [n][co]*1/16, 1=Q -> [n][co], 2=V -> [co][n]
__global__ __launch_bounds__(256)
void proj_kernel(const float* __restrict__ kb, const float* __restrict__ qb,
                 const float* __restrict__ vb) {
    int z = blockIdx.z, b = z / 3, which = z - b * 3;
    int co0 = blockIdx.x * 128, n0 = blockIdx.y * 128;

    if (which == 2) {
        const unsigned short* X = g_Xt + (size_t)b * NN * CI;
        unsigned short* out = g_V + (size_t)b * CO * NN;
        gemm_body(CI / BK, g_Wv + (size_t)co0 * CI, CI, X + (size_t)n0 * CI, CI,
            [&](int row, int col, const float* v) {
                float bv0 = vb[co0 + row], bv1 = vb[co0 + row + 8];
                st_bf16x2(out + (size_t)(co0 + row) * NN + n0 + col, v[0] + bv0, v[1] + bv0);
                st_bf16x2(out + (size_t)(co0 + row + 8) * NN + n0 + col, v[2] + bv1, v[3] + bv1);
            });
    } else {
        const unsigned short* X = (which ? g_Qx : g_Xt) + (size_t)b * NN * CI;
        const unsigned short* W = which ? g_Wq : g_Wk;
        const float* bias = which ? qb : kb;
        unsigned short* out = (which ? g_Qt : g_Kt) + (size_t)b * NN * CO;
        float scale = which ? 1.0f : 0.0625f;
        gemm_body(CI / BK, X + (size_t)n0 * CI, CI, W + (size_t)co0 * CI, CI,
            [&](int row, int col, const float* v) {
                float b0 = bias[co0 + col], b1 = bias[co0 + col + 1];
                st_bf16x2(out + (size_t)(n0 + row) * CO + co0 + col,
                          (v[0] + b0) * scale, (v[1] + b1) * scale);
                st_bf16x2(out + (size_t)(n0 + row + 8) * CO + co0 + col,
                          (v[2] + b0) * scale, (v[3] + b1) * scale);
            });
    }
}

// ---------------- Stage 2: S = exp(K.Q/16), rowsum via atomics ----------------
__global__ __launch_bounds__(256)
void qk_kernel() {
    int b = blockIdx.z;
    const unsigned short* Kt = g_Kt + (size_t)b * NN * CO;
    const unsigned short* Qt = g_Qt + (size_t)b * NN * CO;
    unsigned short* S = g_S + (size_t)b * NN * NN;
    int m0 = blockIdx.x * 128, n0 = blockIdx.y * 128;

    float rs[4] = {0.f, 0.f, 0.f, 0.f};
    gemm_body(CO / BK, Kt + (size_t)n0 * CO, CO, Qt + (size_t)m0 * CO, CO,
        [&](int row, int col, const float* v) {
            float e0 = __expf(v[0]), e1 = __expf(v[1]);
            float e2 = __expf(v[2]), e3 = __expf(v[3]);
            st_bf16x2(S + (size_t)(n0 + row) * NN + m0 + col, e0, e1);
            st_bf16x2(S + (size_t)(n0 + row + 8) * NN + m0 + col, e2, e3);
            rs[(row >> 3) & 3] += e0 + e1;
            rs[((row >> 3) & 3) | 1] += e2 + e3;
        });

    int lane = threadIdx.x & 31, wid = threadIdx.x >> 5;
    int wm = (wid & 3) * 32, q = lane >> 2;
#pragma unroll
    for (int i = 0; i < 4; i++) {
        float s = rs[i];
        s += __shfl_xor_sync(0xffffffffu, s, 1);
        s += __shfl_xor_sync(0xffffffffu, s, 2);
        if ((lane & 3) == 0) {
            int row = wm + (i >> 1) * 16 + (i & 1) * 8 + q;
            atomicAdd(&g_rowsum[(size_t)b * NN + n0 + row], s);
        }
    }
}

// ---------------- Stage 3: O[n][c] = (sum_m e[n][m] V[c][m]) / rowsum[n] ----------------
__global__ __launch_bounds__(256)
void av_kernel() {
    int b = blockIdx.z;
    const unsigned short* P = g_S + (size_t)b * NN * NN;
    const unsigned short* V = g_V + (size_t)b * CO * NN;
    const float* rsum = g_rowsum + (size_t)b * NN;
    unsigned short* O = g_O + (size_t)b * NN * CO;
    int c0 = blockIdx.x * 128, n0 = blockIdx.y * 128;

    gemm_body(NN / BK, P + (size_t)n0 * NN, NN, V + (size_t)c0 * NN, NN,
        [&](int row, int col, const float* v) {
            float i0 = 1.0f / rsum[n0 + row];
            float i1 = 1.0f / rsum[n0 + row + 8];
            st_bf16x2(O + (size_t)(n0 + row) * CO + c0 + col, v[0] * i0, v[1] * i0);
            st_bf16x2(O + (size_t)(n0 + row + 8) * CO + c0 + col, v[2] * i1, v[3] * i1);
        });
}

// ---------------- Stage 4: up-proj + residual ----------------
__global__ __launch_bounds__(256)
void up_kernel(const float* __restrict__ x, const float* __restrict__ up_b,
               const float* __restrict__ scaling, float* __restrict__ outp) {
    int b = blockIdx.z;
    const unsigned short* Ot = g_Ot + (size_t)b * NN * CO;
    const float* X = x + (size_t)b * CI * NN;
    float* R = outp + (size_t)b * CI * NN;
    int n0 = blockIdx.x * 128, ci0 = blockIdx.y * 128;
    float s = *scaling;

    gemm_body(CO / BK, g_Wu + (size_t)ci0 * CO, CO, Ot + (size_t)n0 * CO, CO,
        [&](int row, int col, const float* v) {
#pragma unroll
            for (int h = 0; h < 2; h++) {
                int ci = ci0 + row + h * 8;
                float bb = up_b[ci];
                const float2 xv = *reinterpret_cast<const float2*>(X + (size_t)ci * NN + n0 + col);
                float2 o;
                o.x = xv.x + s * (v[2 * h] + bb);
                o.y = xv.y + s * (v[2 * h + 1] + bb);
                *reinterpret_cast<float2*>(R + (size_t)ci * NN + n0 + col) = o;
            }
        });
}

// ---------------- launch ----------------
extern "C" void kernel_launch(void* const* d_in, const int* in_sizes, int n_in,
                              void* d_out, int out_size) {
    const float* x       = (const float*)d_in[0];
    const float* query   = (const float*)d_in[1];
    const float* key_w   = (const float*)d_in[2];
    const float* key_b   = (const float*)d_in[3];
    const float* val_w   = (const float*)d_in[4];
    const float* val_b   = (const float*)d_in[5];
    const float* query_w = (const float*)d_in[6];
    const float* query_b = (const float*)d_in[7];
    const float* up_w    = (const float*)d_in[8];
    const float* up_b    = (const float*)d_in[9];
    const float* scaling = (const float*)d_in[10];
    float* out = (float*)d_out;

    cudaFuncSetAttribute(proj_kernel, cudaFuncAttributeMaxDynamicSharedMemorySize, SMEM_BYTES);
    cudaFuncSetAttribute(qk_kernel,   cudaFuncAttributeMaxDynamicSharedMemorySize, SMEM_BYTES);
    cudaFuncSetAttribute(av_kernel,   cudaFuncAttributeMaxDynamicSharedMemorySize, SMEM_BYTES);
    cudaFuncSetAttribute(up_kernel,   cudaFuncAttributeMaxDynamicSharedMemorySize, SMEM_BYTES);

    cvt_w<<<2048, 256>>>(key_w, query_w, val_w, up_w);
    zero_rowsum<<<(Bsz * NN) / 64, 64>>>();
    transpose_in<<<dim3(NN / 32, CI / 32, Bsz * 2), 256>>>(x, query);
    proj_kernel<<<dim3(CO / 128, NN / 128, Bsz * 3), 256, SMEM_BYTES>>>(key_b, query_b, val_b);
    qk_kernel<<<dim3(NN / 128, NN / 128, Bsz), 256, SMEM_BYTES>>>();
    av_kernel<<<dim3(CO / 128, NN / 128, Bsz), 256, SMEM_BYTES>>>();
    transpose_o<<<dim3(NN / 32, CO / 32, Bsz), 256>>>();
    up_kernel<<<dim3(NN / 128, CI / 128, Bsz), 256, SMEM_BYTES>>>(x, up_b, scaling, out);
}

// round 8
// speedup vs baseline: 5.5140x; 1.0180x over previous
#include <cuda_runtime.h>
#include <cuda_bf16.h>
#include <cstdint>

#define Bsz 8
#define CI  512
#define CO  256
#define NN  2048

// ---------------- scratch (device globals, bf16) ----------------
__device__ unsigned short g_Xt[(size_t)Bsz * NN * CI];  // [b][n][ci]
__device__ unsigned short g_Qx[(size_t)Bsz * NN * CI];  // [b][n][ci] (query input)
__device__ unsigned short g_Wk[CO * CI];
__device__ unsigned short g_Wq[CO * CI];
__device__ unsigned short g_Wv[CO * CI];
__device__ unsigned short g_Wu[CI * CO];
__device__ unsigned short g_Kt[(size_t)Bsz * NN * CO];  // [b][n][co], pre-scaled 1/16
__device__ unsigned short g_Qt[(size_t)Bsz * NN * CO];  // [b][n][co]
__device__ unsigned short g_V [(size_t)Bsz * CO * NN];  // [b][co][n]
__device__ unsigned short g_S [(size_t)Bsz * NN * NN];  // [b][n][m] exp(logits)
__device__ unsigned short g_O [(size_t)Bsz * NN * CO];  // [b][n][co]; raw view == [co2][n2]
__device__ unsigned short g_Ot[(size_t)Bsz * NN * CO];  // [b][n2][co2]
__device__ float          g_rowsum[(size_t)Bsz * NN];

// ---------------- helpers ----------------
__device__ __forceinline__ uint32_t smem_u32(const void* p) {
    uint32_t a;
    asm("{ .reg .u64 t; cvta.to.shared.u64 t, %1; cvt.u32.u64 %0, t; }" : "=r"(a) : "l"(p));
    return a;
}
__device__ __forceinline__ void ldmatrix_x4(uint32_t* r, uint32_t addr) {
    asm volatile("ldmatrix.sync.aligned.m8n8.x4.shared.b16 {%0,%1,%2,%3}, [%4];"
                 : "=r"(r[0]), "=r"(r[1]), "=r"(r[2]), "=r"(r[3]) : "r"(addr));
}
__device__ __forceinline__ void mma16816(float* d, const uint32_t* a, const uint32_t* b) {
    asm volatile(
        "mma.sync.aligned.m16n8k16.row.col.f32.bf16.bf16.f32 "
        "{%0,%1,%2,%3}, {%4,%5,%6,%7}, {%8,%9}, {%0,%1,%2,%3};"
        : "+f"(d[0]), "+f"(d[1]), "+f"(d[2]), "+f"(d[3])
        : "r"(a[0]), "r"(a[1]), "r"(a[2]), "r"(a[3]), "r"(b[0]), "r"(b[1]));
}
__device__ __forceinline__ void st_bf16x2(unsigned short* dst, float v0, float v1) {
    __nv_bfloat162 h = __floats2bfloat162_rn(v0, v1);
    *reinterpret_cast<uint32_t*>(dst) = *reinterpret_cast<uint32_t*>(&h);
}

// smem tile: 128 rows x 64 halves (BK), padded to 72 halves = 144 B/row (9x16B)
#define BK      64
#define ROWB    144
#define TILE_H  (128 * 72)            // halves per tile
#define STAGE_H (2 * TILE_H)          // A + B
#define NSTAGE  3
#define SMEM_BYTES (NSTAGE * STAGE_H * 2)   // 110592

// 128x64 bf16 tile via cp.async: 1024 16-byte chunks, 4 per thread
__device__ __forceinline__ void cp_tile(uint32_t sb, const unsigned short* __restrict__ src,
                                        int ld, int tid) {
#pragma unroll
    for (int i = 0; i < 4; i++) {
        int ch = tid + i * 256;
        int row = ch >> 3, c = ch & 7;
        uint32_t sa = sb + row * ROWB + c * 16;
        const void* ga = src + (size_t)row * ld + c * 8;
        asm volatile("cp.async.cg.shared.global [%0], [%1], 16;" :: "r"(sa), "l"(ga));
    }
}

// load one ks-step's fragments (A 2x, B 4x ldmatrix.x4)
__device__ __forceinline__ void load_frags(uint32_t aB, uint32_t bB, int ks,
                                           int wm, int wn, int lane,
                                           uint32_t a[2][4], uint32_t b[8][2]) {
#pragma unroll
    for (int mt = 0; mt < 2; mt++) {
        uint32_t addr = aB + (wm + mt * 16 + (lane & 15)) * ROWB
                      + (ks * 16 + ((lane >> 4) << 3)) * 2;
        ldmatrix_x4(a[mt], addr);
    }
#pragma unroll
    for (int np = 0; np < 4; np++) {
        uint32_t r[4];
        int row = wn + np * 16 + ((lane >> 4) << 3) + (lane & 7);
        int koff = ks * 16 + (((lane >> 3) & 1) << 3);
        ldmatrix_x4(r, bB + row * ROWB + koff * 2);
        b[2 * np][0] = r[0]; b[2 * np][1] = r[1];
        b[2 * np + 1][0] = r[2]; b[2 * np + 1][1] = r[3];
    }
}

// ---------------- 3-stage pipelined 128x128 HMMA GEMM, BK=64 ----------------
// D[m][n] = sum_k A[m][k] * B[n][k]; A,B row-major bf16.
// warp grid 4x2, warp tile 32(m) x 64(n); fragment-level double buffering.
// fe(r0, col, v): v = {D[r0][col], D[r0][col+1], D[r0+8][col], D[r0+8][col+1]}
template <class FE>
__device__ __forceinline__ void gemm_body(int ktiles,
        const unsigned short* __restrict__ Ag, int lda,
        const unsigned short* __restrict__ Bg, int ldb, FE fe) {
    extern __shared__ __align__(16) unsigned short sm[];
    const int tid = threadIdx.x, wid = tid >> 5, lane = tid & 31;
    const int wm = (wid & 3) * 32, wn = (wid >> 2) * 64;

    float acc[2][8][4];
#pragma unroll
    for (int mt = 0; mt < 2; mt++)
#pragma unroll
        for (int nt = 0; nt < 8; nt++)
#pragma unroll
            for (int j = 0; j < 4; j++) acc[mt][nt][j] = 0.f;

#pragma unroll
    for (int s = 0; s < 2; s++) {
        uint32_t sb = smem_u32(sm + s * STAGE_H);
        cp_tile(sb, Ag + (size_t)s * BK, lda, tid);
        cp_tile(sb + TILE_H * 2, Bg + (size_t)s * BK, ldb, tid);
        asm volatile("cp.async.commit_group;" ::: "memory");
    }

    uint32_t fa[2][2][4], fb[2][8][2];
    int stage = 0;
    for (int kt = 0; kt < ktiles; kt++) {
        if (kt == ktiles - 1) asm volatile("cp.async.wait_group 0;" ::: "memory");
        else                  asm volatile("cp.async.wait_group 1;" ::: "memory");
        __syncthreads();

        if (kt + 2 < ktiles) {
            int ps = stage + 2; if (ps >= NSTAGE) ps -= NSTAGE;
            uint32_t sb = smem_u32(sm + ps * STAGE_H);
            cp_tile(sb, Ag + (size_t)(kt + 2) * BK, lda, tid);
            cp_tile(sb + TILE_H * 2, Bg + (size_t)(kt + 2) * BK, ldb, tid);
            asm volatile("cp.async.commit_group;" ::: "memory");
        }

        const uint32_t aB = smem_u32(sm + stage * STAGE_H);
        const uint32_t bB = aB + TILE_H * 2;

        load_frags(aB, bB, 0, wm, wn, lane, fa[0], fb[0]);
#pragma unroll
        for (int ks = 0; ks < 4; ks++) {
            int cb = ks & 1;
            if (ks < 3)
                load_frags(aB, bB, ks + 1, wm, wn, lane, fa[cb ^ 1], fb[cb ^ 1]);
#pragma unroll
            for (int mt = 0; mt < 2; mt++)
#pragma unroll
                for (int nt = 0; nt < 8; nt++)
                    mma16816(acc[mt][nt], fa[cb][mt], fb[cb][nt]);
        }
        if (++stage == NSTAGE) stage = 0;
    }

#pragma unroll
    for (int mt = 0; mt < 2; mt++) {
        int r0 = wm + mt * 16 + (lane >> 2);
#pragma unroll
        for (int nt = 0; nt < 8; nt++)
            fe(r0, wn + nt * 8 + ((lane & 3) << 1), acc[mt][nt]);
    }
}

// ---------------- small pre/mid passes ----------------
__global__ __launch_bounds__(256)
void cvt_w(const float* __restrict__ kw, const float* __restrict__ qw,
           const float* __restrict__ vw, const float* __restrict__ uw) {
    int idx = blockIdx.x * 256 + threadIdx.x;
    int seg = idx >> 17, off = idx & 131071;
    const float* src = seg == 0 ? kw : seg == 1 ? qw : seg == 2 ? vw : uw;
    unsigned short* dst = seg == 0 ? g_Wk : seg == 1 ? g_Wq : seg == 2 ? g_Wv : g_Wu;
    __nv_bfloat16 h = __float2bfloat16(src[off]);
    dst[off] = *reinterpret_cast<unsigned short*>(&h);
}

__global__ __launch_bounds__(64)
void zero_rowsum() { g_rowsum[blockIdx.x * 64 + threadIdx.x] = 0.f; }

__global__ __launch_bounds__(256)
void transpose_in(const float* __restrict__ x, const float* __restrict__ query) {
    int z = blockIdx.z, b = z >> 1, which = z & 1;
    const float* src = (which ? query : x) + (size_t)b * CI * NN;
    unsigned short* dst = (which ? g_Qx : g_Xt) + (size_t)b * NN * CI;
    __shared__ unsigned short t[32][33];
    int n0 = blockIdx.x * 32, c0 = blockIdx.y * 32;
    int tx = threadIdx.x & 31, ty = threadIdx.x >> 5;
#pragma unroll
    for (int j = 0; j < 4; j++) {
        int ci = c0 + ty + j * 8;
        __nv_bfloat16 h = __float2bfloat16(src[(size_t)ci * NN + n0 + tx]);
        t[ty + j * 8][tx] = *reinterpret_cast<unsigned short*>(&h);
    }
    __syncthreads();
#pragma unroll
    for (int j = 0; j < 4; j++)
        dst[(size_t)(n0 + ty + j * 8) * CI + c0 + tx] = t[tx][ty + j * 8];
}

__global__ __launch_bounds__(256)
void transpose_o() {
    int b = blockIdx.z;
    const unsigned short* src = g_O + (size_t)b * NN * CO;  // [co2][n2], ld = NN
    unsigned short* dst = g_Ot + (size_t)b * NN * CO;       // [n2][co2], ld = CO
    __shared__ unsigned short t[32][33];
    int n0 = blockIdx.x * 32, c0 = blockIdx.y * 32;
    int tx = threadIdx.x & 31, ty = threadIdx.x >> 5;
#pragma unroll
    for (int j = 0; j < 4; j++)
        t[ty + j * 8][tx] = src[(size_t)(c0 + ty + j * 8) * NN + n0 + tx];
    __syncthreads();
#pragma unroll
    for (int j = 0; j < 4; j++)
        dst[(size_t)(n0 + ty + j * 8) * CO + c0 + tx] = t[tx][ty + j * 8];
}

// ---------------- Stage 1: ALL projections in one launch ----------------
// z = b*3 + which; which: 0=K -> [n][co]*1/16, 1=Q -> [n][co], 2=V -> [co][n]
__global__ __launch_bounds__(256, 2)
void proj_kernel(const float* __restrict__ kb, const float* __restrict__ qb,
                 const float* __restrict__ vb) {
    int z = blockIdx.z, b = z / 3, which = z - b * 3;
    int co0 = blockIdx.x * 128, n0 = blockIdx.y * 128;

    if (which == 2) {
        const unsigned short* X = g_Xt + (size_t)b * NN * CI;
        unsigned short* out = g_V + (size_t)b * CO * NN;
        gemm_body(CI / BK, g_Wv + (size_t)co0 * CI, CI, X + (size_t)n0 * CI, CI,
            [&](int row, int col, const float* v) {
                float bv0 = vb[co0 + row], bv1 = vb[co0 + row + 8];
                st_bf16x2(out + (size_t)(co0 + row) * NN + n0 + col, v[0] + bv0, v[1] + bv0);
                st_bf16x2(out + (size_t)(co0 + row + 8) * NN + n0 + col, v[2] + bv1, v[3] + bv1);
            });
    } else {
        const unsigned short* X = (which ? g_Qx : g_Xt) + (size_t)b * NN * CI;
        const unsigned short* W = which ? g_Wq : g_Wk;
        const float* bias = which ? qb : kb;
        unsigned short* out = (which ? g_Qt : g_Kt) + (size_t)b * NN * CO;
        float scale = which ? 1.0f : 0.0625f;
        gemm_body(CI / BK, X + (size_t)n0 * CI, CI, W + (size_t)co0 * CI, CI,
            [&](int row, int col, const float* v) {
                float b0 = bias[co0 + col], b1 = bias[co0 + col + 1];
                st_bf16x2(out + (size_t)(n0 + row) * CO + co0 + col,
                          (v[0] + b0) * scale, (v[1] + b1) * scale);
                st_bf16x2(out + (size_t)(n0 + row + 8) * CO + co0 + col,
                          (v[2] + b0) * scale, (v[3] + b1) * scale);
            });
    }
}

// ---------------- Stage 2: S = exp(K.Q/16), rowsum via atomics ----------------
__global__ __launch_bounds__(256, 2)
void qk_kernel() {
    int b = blockIdx.z;
    const unsigned short* Kt = g_Kt + (size_t)b * NN * CO;
    const unsigned short* Qt = g_Qt + (size_t)b * NN * CO;
    unsigned short* S = g_S + (size_t)b * NN * NN;
    int m0 = blockIdx.x * 128, n0 = blockIdx.y * 128;

    float rs[4] = {0.f, 0.f, 0.f, 0.f};
    gemm_body(CO / BK, Kt + (size_t)n0 * CO, CO, Qt + (size_t)m0 * CO, CO,
        [&](int row, int col, const float* v) {
            float e0 = __expf(v[0]), e1 = __expf(v[1]);
            float e2 = __expf(v[2]), e3 = __expf(v[3]);
            st_bf16x2(S + (size_t)(n0 + row) * NN + m0 + col, e0, e1);
            st_bf16x2(S + (size_t)(n0 + row + 8) * NN + m0 + col, e2, e3);
            rs[(row >> 3) & 3] += e0 + e1;
            rs[((row >> 3) & 3) | 1] += e2 + e3;
        });

    int lane = threadIdx.x & 31, wid = threadIdx.x >> 5;
    int wm = (wid & 3) * 32, q = lane >> 2;
#pragma unroll
    for (int i = 0; i < 4; i++) {
        float s = rs[i];
        s += __shfl_xor_sync(0xffffffffu, s, 1);
        s += __shfl_xor_sync(0xffffffffu, s, 2);
        if ((lane & 3) == 0) {
            int row = wm + (i >> 1) * 16 + (i & 1) * 8 + q;
            atomicAdd(&g_rowsum[(size_t)b * NN + n0 + row], s);
        }
    }
}

// ---------------- Stage 3: O[n][c] = (sum_m e[n][m] V[c][m]) / rowsum[n] ----------------
__global__ __launch_bounds__(256, 2)
void av_kernel() {
    int b = blockIdx.z;
    const unsigned short* P = g_S + (size_t)b * NN * NN;
    const unsigned short* V = g_V + (size_t)b * CO * NN;
    const float* rsum = g_rowsum + (size_t)b * NN;
    unsigned short* O = g_O + (size_t)b * NN * CO;
    int c0 = blockIdx.x * 128, n0 = blockIdx.y * 128;

    gemm_body(NN / BK, P + (size_t)n0 * NN, NN, V + (size_t)c0 * NN, NN,
        [&](int row, int col, const float* v) {
            float i0 = 1.0f / rsum[n0 + row];
            float i1 = 1.0f / rsum[n0 + row + 8];
            st_bf16x2(O + (size_t)(n0 + row) * CO + c0 + col, v[0] * i0, v[1] * i0);
            st_bf16x2(O + (size_t)(n0 + row + 8) * CO + c0 + col, v[2] * i1, v[3] * i1);
        });
}

// ---------------- Stage 4: up-proj + residual ----------------
__global__ __launch_bounds__(256, 2)
void up_kernel(const float* __restrict__ x, const float* __restrict__ up_b,
               const float* __restrict__ scaling, float* __restrict__ outp) {
    int b = blockIdx.z;
    const unsigned short* Ot = g_Ot + (size_t)b * NN * CO;
    const float* X = x + (size_t)b * CI * NN;
    float* R = outp + (size_t)b * CI * NN;
    int n0 = blockIdx.x * 128, ci0 = blockIdx.y * 128;
    float s = *scaling;

    gemm_body(CO / BK, g_Wu + (size_t)ci0 * CO, CO, Ot + (size_t)n0 * CO, CO,
        [&](int row, int col, const float* v) {
#pragma unroll
            for (int h = 0; h < 2; h++) {
                int ci = ci0 + row + h * 8;
                float bb = up_b[ci];
                const float2 xv = *reinterpret_cast<const float2*>(X + (size_t)ci * NN + n0 + col);
                float2 o;
                o.x = xv.x + s * (v[2 * h] + bb);
                o.y = xv.y + s * (v[2 * h + 1] + bb);
                *reinterpret_cast<float2*>(R + (size_t)ci * NN + n0 + col) = o;
            }
        });
}

// ---------------- launch ----------------
extern "C" void kernel_launch(void* const* d_in, const int* in_sizes, int n_in,
                              void* d_out, int out_size) {
    const float* x       = (const float*)d_in[0];
    const float* query   = (const float*)d_in[1];
    const float* key_w   = (const float*)d_in[2];
    const float* key_b   = (const float*)d_in[3];
    const float* val_w   = (const float*)d_in[4];
    const float* val_b   = (const float*)d_in[5];
    const float* query_w = (const float*)d_in[6];
    const float* query_b = (const float*)d_in[7];
    const float* up_w    = (const float*)d_in[8];
    const float* up_b    = (const float*)d_in[9];
    const float* scaling = (const float*)d_in[10];
    float* out = (float*)d_out;

    cudaFuncSetAttribute(proj_kernel, cudaFuncAttributeMaxDynamicSharedMemorySize, SMEM_BYTES);
    cudaFuncSetAttribute(qk_kernel,   cudaFuncAttributeMaxDynamicSharedMemorySize, SMEM_BYTES);
    cudaFuncSetAttribute(av_kernel,   cudaFuncAttributeMaxDynamicSharedMemorySize, SMEM_BYTES);
    cudaFuncSetAttribute(up_kernel,   cudaFuncAttributeMaxDynamicSharedMemorySize, SMEM_BYTES);

    cvt_w<<<2048, 256>>>(key_w, query_w, val_w, up_w);
    zero_rowsum<<<(Bsz * NN) / 64, 64>>>();
    transpose_in<<<dim3(NN / 32, CI / 32, Bsz * 2), 256>>>(x, query);
    proj_kernel<<<dim3(CO / 128, NN / 128, Bsz * 3), 256, SMEM_BYTES>>>(key_b, query_b, val_b);
    qk_kernel<<<dim3(NN / 128, NN / 128, Bsz), 256, SMEM_BYTES>>>();
    av_kernel<<<dim3(CO / 128, NN / 128, Bsz), 256, SMEM_BYTES>>>();
    transpose_o<<<dim3(NN / 32, CO / 32, Bsz), 256>>>();
    up_kernel<<<dim3(NN / 128, CI / 128, Bsz), 256, SMEM_BYTES>>>(x, up_b, scaling, out);
}